// round 4
// baseline (speedup 1.0000x reference)
#include <cuda_runtime.h>
#include <cstdint>
#include <cstddef>

// Problem constants
#define BB 4
#define TT 2048
#define CC 1024
#define HH 16
#define DD 64
#define C3 (3 * CC)

// Scratch (allocation-free rule: __device__ globals)
__device__ float g_kqv[(size_t)BB * TT * C3];  // [B,T,3C]  (k | q | v)
__device__ float g_y[(size_t)BB * TT * CC];    // [B,T,C]

// ---------------------------------------------------------------------------
// TF32 tensor-core GEMM with bias: C[M,N] = A[M,K] @ B[K,N] + bias[N]
// Block tile 128x128, BK=32, 256 threads (8 warps), warp tile 64x32.
// Fragments stored in smem in register-fragment order (conflict-free LDS.128).
// Requires M%128==0, N%128==0, K%32==0.
// ---------------------------------------------------------------------------
__device__ __forceinline__ uint32_t f2tf32(float x) {
    uint32_t r;
    asm("cvt.rna.tf32.f32 %0, %1;" : "=r"(r) : "f"(x));
    return r;
}

__device__ __forceinline__ void mma_tf32(float* d, const uint32_t* a, const uint32_t* b) {
    asm volatile(
        "mma.sync.aligned.m16n8k8.row.col.f32.tf32.tf32.f32 "
        "{%0,%1,%2,%3}, {%4,%5,%6,%7}, {%8,%9}, {%0,%1,%2,%3};"
        : "+f"(d[0]), "+f"(d[1]), "+f"(d[2]), "+f"(d[3])
        : "r"(a[0]), "r"(a[1]), "r"(a[2]), "r"(a[3]), "r"(b[0]), "r"(b[1]));
}

__global__ void __launch_bounds__(256, 2) gemm_tf32_bias(
    const float* __restrict__ A, const float* __restrict__ Bm,
    const float* __restrict__ bias, float* __restrict__ Cm,
    int M, int N, int K)
{
    // Fragment-ordered smem:
    // A: [mtile(8)][ksub(4)][lane(32)] x uint4   -> 4096 u32
    // B: [ntile(16)][ksub(4)][lane(32)] x uint2  -> 4096 u32
    __shared__ uint32_t As[4096];
    __shared__ uint32_t Bs[4096];

    const int tid  = threadIdx.x;
    const int warp = tid >> 5;
    const int lane = tid & 31;
    const int bm = blockIdx.y * 128;
    const int bn = blockIdx.x * 128;

    const int warpM = (warp >> 2) * 64;   // 0 or 64
    const int warpN = (warp & 3) * 32;    // 0,32,64,96
    const int warpMt = (warp >> 2) * 4;   // base mtile
    const int warpNt = (warp & 3) * 4;    // base ntile

    // Global loader mapping
    const int arow = tid >> 1;            // 0..127
    const int akb  = (tid & 1) * 16;      // 0 or 16
    const int brow = tid >> 3;            // 0..31
    const int bcb  = (tid & 7) * 16;      // 0..112

    const float* agp = A + (size_t)(bm + arow) * K + akb;
    const float* bgp = Bm + (size_t)brow * N + bn + bcb;

    // Precompute smem store bases (element offsets) for the 4 float4s each
    int a_base[4], b_base[4];
    {
        const int mt = arow >> 4;
        const int r  = arow & 15;
        const int lanebA = (r & 7) * 4;
        const int ridx = r >> 3;
#pragma unroll
        for (int j = 0; j < 4; j++) {
            const int k = akb + 4 * j;
            const int kc = k >> 3;
            const int aidx = ridx + ((k >> 2) & 1) * 2;
            a_base[j] = ((mt * 4 + kc) * 32 + lanebA) * 4 + aidx;
        }
        const int k = brow;
        const int kc = k >> 3;
        const int bidx = (k >> 2) & 1;
#pragma unroll
        for (int j = 0; j < 4; j++) {
            const int n = bcb + 4 * j;
            const int nt = n >> 3;
            const int lanebB = (n & 7) * 4 + (k & 3);
            b_base[j] = ((nt * 4 + kc) * 32 + lanebB) * 2 + bidx;
        }
    }

    float cacc[4][4][4];
#pragma unroll
    for (int i = 0; i < 4; i++)
#pragma unroll
        for (int j = 0; j < 4; j++)
#pragma unroll
            for (int e = 0; e < 4; e++) cacc[i][j][e] = 0.0f;

    float4 apf[4], bpf[4];
    // Prologue: load K-tile 0
#pragma unroll
    for (int j = 0; j < 4; j++) {
        apf[j] = *(const float4*)(agp + 4 * j);
        bpf[j] = *(const float4*)(bgp + (size_t)4 * j);
    }
    agp += 32;
    bgp += (size_t)32 * N;
    // Store to smem (with tf32 cvt)
#pragma unroll
    for (int j = 0; j < 4; j++) {
        As[a_base[j] + 0]  = f2tf32(apf[j].x);
        As[a_base[j] + 4]  = f2tf32(apf[j].y);
        As[a_base[j] + 8]  = f2tf32(apf[j].z);
        As[a_base[j] + 12] = f2tf32(apf[j].w);
        Bs[b_base[j] + 0]  = f2tf32(bpf[j].x);
        Bs[b_base[j] + 8]  = f2tf32(bpf[j].y);
        Bs[b_base[j] + 16] = f2tf32(bpf[j].z);
        Bs[b_base[j] + 24] = f2tf32(bpf[j].w);
    }
    __syncthreads();

    for (int k0 = 32; k0 <= K; k0 += 32) {
        const bool more = (k0 < K);
        if (more) {
#pragma unroll
            for (int j = 0; j < 4; j++) {
                apf[j] = *(const float4*)(agp + 4 * j);
                bpf[j] = *(const float4*)(bgp + (size_t)4 * j);
            }
            agp += 32;
            bgp += (size_t)32 * N;
        }

        // MMA over current smem tile
#pragma unroll
        for (int kc = 0; kc < 4; kc++) {
            uint32_t af[4][4];
            uint32_t bf[4][2];
#pragma unroll
            for (int mt4 = 0; mt4 < 4; mt4++) {
                const int idx = ((warpMt + mt4) * 4 + kc) * 32 + lane;
                *(uint4*)af[mt4] = *(const uint4*)&As[idx * 4];
            }
#pragma unroll
            for (int nt4 = 0; nt4 < 4; nt4++) {
                const int idx = ((warpNt + nt4) * 4 + kc) * 32 + lane;
                *(uint2*)bf[nt4] = *(const uint2*)&Bs[idx * 2];
            }
#pragma unroll
            for (int mt4 = 0; mt4 < 4; mt4++)
#pragma unroll
                for (int nt4 = 0; nt4 < 4; nt4++)
                    mma_tf32(cacc[mt4][nt4], af[mt4], bf[nt4]);
        }

        if (more) {
            __syncthreads();
#pragma unroll
            for (int j = 0; j < 4; j++) {
                As[a_base[j] + 0]  = f2tf32(apf[j].x);
                As[a_base[j] + 4]  = f2tf32(apf[j].y);
                As[a_base[j] + 8]  = f2tf32(apf[j].z);
                As[a_base[j] + 12] = f2tf32(apf[j].w);
                Bs[b_base[j] + 0]  = f2tf32(bpf[j].x);
                Bs[b_base[j] + 8]  = f2tf32(bpf[j].y);
                Bs[b_base[j] + 16] = f2tf32(bpf[j].z);
                Bs[b_base[j] + 24] = f2tf32(bpf[j].w);
            }
            __syncthreads();
        }
    }

    // Epilogue: C = acc + bias
    const int crow = lane >> 2;
    const int ccol = (lane & 3) * 2;
#pragma unroll
    for (int mt4 = 0; mt4 < 4; mt4++) {
#pragma unroll
        for (int nt4 = 0; nt4 < 4; nt4++) {
            const int grow = bm + warpM + mt4 * 16 + crow;
            const int gcol = bn + warpN + nt4 * 8 + ccol;
            const float b0 = bias[gcol];
            const float b1 = bias[gcol + 1];
            float2 v0, v1;
            v0.x = cacc[mt4][nt4][0] + b0;
            v0.y = cacc[mt4][nt4][1] + b1;
            v1.x = cacc[mt4][nt4][2] + b0;
            v1.y = cacc[mt4][nt4][3] + b1;
            *(float2*)(Cm + (size_t)grow * N + gcol) = v0;
            *(float2*)(Cm + (size_t)(grow + 8) * N + gcol) = v1;
        }
    }
}

// ---------------------------------------------------------------------------
// Flash attention (fp32, online softmax), BQ=64 x BK=32 tiles. (unchanged)
// ---------------------------------------------------------------------------
#define BQ 64
#define BK 32

__global__ void __launch_bounds__(256) attn_kernel(
    const float* __restrict__ kqv, const int* __restrict__ padmask,
    float* __restrict__ y)
{
    __shared__ float Qs[BQ][DD + 1];
    __shared__ float Ks[BK][DD + 1];
    __shared__ float Vs[BK][DD + 1];
    __shared__ float Ps[BQ][BK + 1];
    __shared__ float red[BQ][17];
    __shared__ float m_s[BQ], l_s[BQ], alpha_s[BQ];
    __shared__ int   padv[BK];

    const int q0 = blockIdx.x * BQ;
    const int h  = blockIdx.y;
    const int b  = blockIdx.z;
    const int tid = threadIdx.x;
    const int tr = tid >> 4;
    const int tc = tid & 15;
    const float scale = 0.125f;  // 1/sqrt(64)

    const float* base = kqv + (size_t)b * TT * C3 + (size_t)h * DD;
    const float* qbase = base + CC;       // q segment
    const float* kbase = base;            // k segment
    const float* vbase = base + 2 * CC;   // v segment

    for (int i = tid; i < BQ * (DD / 4); i += 256) {
        int r = i >> 4, c4 = (i & 15) << 2;
        float4 v = *(const float4*)(qbase + (size_t)(q0 + r) * C3 + c4);
        Qs[r][c4 + 0] = v.x; Qs[r][c4 + 1] = v.y;
        Qs[r][c4 + 2] = v.z; Qs[r][c4 + 3] = v.w;
    }
    if (tid < BQ) { m_s[tid] = -1e30f; l_s[tid] = 0.0f; }

    float o[4][4];
#pragma unroll
    for (int i = 0; i < 4; i++)
#pragma unroll
        for (int j = 0; j < 4; j++) o[i][j] = 0.0f;
    __syncthreads();

    const int jend = q0 + BQ;
    for (int j0 = 0; j0 < jend; j0 += BK) {
        for (int i = tid; i < BK * (DD / 4); i += 256) {
            int r = i >> 4, c4 = (i & 15) << 2;
            size_t off = (size_t)(j0 + r) * C3 + c4;
            float4 kv = *(const float4*)(kbase + off);
            float4 vv = *(const float4*)(vbase + off);
            Ks[r][c4 + 0] = kv.x; Ks[r][c4 + 1] = kv.y;
            Ks[r][c4 + 2] = kv.z; Ks[r][c4 + 3] = kv.w;
            Vs[r][c4 + 0] = vv.x; Vs[r][c4 + 1] = vv.y;
            Vs[r][c4 + 2] = vv.z; Vs[r][c4 + 3] = vv.w;
        }
        if (tid < BK) padv[tid] = padmask[b * TT + j0 + tid];
        __syncthreads();

        float s[4][2];
#pragma unroll
        for (int i = 0; i < 4; i++) { s[i][0] = 0.0f; s[i][1] = 0.0f; }
#pragma unroll 8
        for (int d = 0; d < DD; d++) {
            float qv[4], kv[2];
#pragma unroll
            for (int ri = 0; ri < 4; ri++) qv[ri] = Qs[tr * 4 + ri][d];
            kv[0] = Ks[tc * 2 + 0][d];
            kv[1] = Ks[tc * 2 + 1][d];
#pragma unroll
            for (int ri = 0; ri < 4; ri++) {
                s[ri][0] = fmaf(qv[ri], kv[0], s[ri][0]);
                s[ri][1] = fmaf(qv[ri], kv[1], s[ri][1]);
            }
        }

#pragma unroll
        for (int ri = 0; ri < 4; ri++) {
            const int row = tr * 4 + ri;
            const int qi = q0 + row;
            float pm = -1e30f;
#pragma unroll
            for (int ci = 0; ci < 2; ci++) {
                const int col = tc * 2 + ci;
                const int kj = j0 + col;
                const bool valid = (kj <= qi) && (padv[col] != 0);
                float val = valid ? s[ri][ci] * scale : -1e30f;
                Ps[row][col] = val;
                pm = fmaxf(pm, val);
            }
            red[row][tc] = pm;
        }
        __syncthreads();

        if (tid < BQ) {
            float mmax = m_s[tid];
#pragma unroll
            for (int t = 0; t < 16; t++) mmax = fmaxf(mmax, red[tid][t]);
            alpha_s[tid] = __expf(m_s[tid] - mmax);
            m_s[tid] = mmax;
        }
        __syncthreads();

#pragma unroll
        for (int ri = 0; ri < 4; ri++) {
            const int row = tr * 4 + ri;
            const float mrow = m_s[row];
            const float a = alpha_s[row];
            float ps = 0.0f;
#pragma unroll
            for (int ci = 0; ci < 2; ci++) {
                const int col = tc * 2 + ci;
                float p = __expf(Ps[row][col] - mrow);
                Ps[row][col] = p;
                ps += p;
            }
            red[row][tc] = ps;
#pragma unroll
            for (int ci = 0; ci < 4; ci++) o[ri][ci] *= a;
        }
        __syncthreads();

        if (tid < BQ) {
            float sum = 0.0f;
#pragma unroll
            for (int t = 0; t < 16; t++) sum += red[tid][t];
            l_s[tid] = l_s[tid] * alpha_s[tid] + sum;
        }

#pragma unroll 4
        for (int j = 0; j < BK; j++) {
            float pv[4], vv[4];
#pragma unroll
            for (int ri = 0; ri < 4; ri++) pv[ri] = Ps[tr * 4 + ri][j];
#pragma unroll
            for (int ci = 0; ci < 4; ci++) vv[ci] = Vs[j][tc * 4 + ci];
#pragma unroll
            for (int ri = 0; ri < 4; ri++)
#pragma unroll
                for (int ci = 0; ci < 4; ci++)
                    o[ri][ci] = fmaf(pv[ri], vv[ci], o[ri][ci]);
        }
        __syncthreads();
    }

#pragma unroll
    for (int ri = 0; ri < 4; ri++) {
        const int row = tr * 4 + ri;
        const float inv = 1.0f / l_s[row];
        float* yp = y + ((size_t)b * TT + q0 + row) * CC + h * DD + tc * 4;
        float4 v;
        v.x = o[ri][0] * inv; v.y = o[ri][1] * inv;
        v.z = o[ri][2] * inv; v.w = o[ri][3] * inv;
        *(float4*)yp = v;
    }
}

// ---------------------------------------------------------------------------
extern "C" void kernel_launch(void* const* d_in, const int* in_sizes, int n_in,
                              void* d_out, int out_size)
{
    const float* x      = (const float*)d_in[0];
    const float* W_kqv  = (const float*)d_in[1];
    const float* b_kqv  = (const float*)d_in[2];
    const float* W_proj = (const float*)d_in[3];
    const float* b_proj = (const float*)d_in[4];
    const int*   pad    = (const int*)d_in[5];
    float* out = (float*)d_out;

    float* kqv_ptr = nullptr;
    float* y_ptr = nullptr;
    cudaGetSymbolAddress((void**)&kqv_ptr, g_kqv);
    cudaGetSymbolAddress((void**)&y_ptr, g_y);

    const int M = BB * TT;  // 8192

    // 1) kqv = x @ W_kqv + b_kqv   [8192, 3072]
    {
        dim3 grid(C3 / 128, M / 128);
        gemm_tf32_bias<<<grid, 256>>>(x, W_kqv, b_kqv, kqv_ptr, M, C3, CC);
    }
    // 2) flash attention -> y  [8192, 1024]
    {
        dim3 grid(TT / BQ, HH, BB);
        attn_kernel<<<grid, 256>>>(kqv_ptr, pad, y_ptr);
    }
    // 3) out = y @ W_proj + b_proj  [8192, 1024]
    {
        dim3 grid(CC / 128, M / 128);
        gemm_tf32_bias<<<grid, 256>>>(y_ptr, W_proj, b_proj, out, M, CC, CC);
    }
}

// round 5
// speedup vs baseline: 1.6115x; 1.6115x over previous
#include <cuda_runtime.h>
#include <cstdint>
#include <cstddef>

// Problem constants
#define BB 4
#define TT 2048
#define CC 1024
#define HH 16
#define DD 64
#define C3 (3 * CC)

// Scratch (allocation-free rule: __device__ globals)
__device__ float g_kqv[(size_t)BB * TT * C3];  // [B,T,3C]  (k | q | v)
__device__ float g_y[(size_t)BB * TT * CC];    // [B,T,C]

// ---------------------------------------------------------------------------
// TF32 tensor-core GEMM with bias: C[M,N] = A[M,K] @ B[K,N] + bias[N]
// Block tile 128x128, BK=32, 256 threads (8 warps), warp tile 64x32.
// Double-buffered fragment-ordered smem (conflict-free LDS.128 / LDS.64),
// ONE __syncthreads per K-tile so STS + gmem loads overlap the MMA block.
// Requires M%128==0, N%128==0, K%32==0.
// ---------------------------------------------------------------------------
__device__ __forceinline__ uint32_t f2tf32(float x) {
    uint32_t r;
    asm("cvt.rna.tf32.f32 %0, %1;" : "=r"(r) : "f"(x));
    return r;
}

__device__ __forceinline__ void mma_tf32(float* d, const uint32_t* a, const uint32_t* b) {
    asm volatile(
        "mma.sync.aligned.m16n8k8.row.col.f32.tf32.tf32.f32 "
        "{%0,%1,%2,%3}, {%4,%5,%6,%7}, {%8,%9}, {%0,%1,%2,%3};"
        : "+f"(d[0]), "+f"(d[1]), "+f"(d[2]), "+f"(d[3])
        : "r"(a[0]), "r"(a[1]), "r"(a[2]), "r"(a[3]), "r"(b[0]), "r"(b[1]));
}

// Dynamic smem layout (u32 elements):
//   As stage s: [s*4096 .. ]      A: [mtile(8)][ksub(4)][lane(32)] x 4 regs
//   Bs stage s: [8192 + s*4096 ]  B: [ntile(16)][ksub(4)][lane(32)] x 2 regs
__global__ void __launch_bounds__(256, 2) gemm_tf32_bias(
    const float* __restrict__ A, const float* __restrict__ Bm,
    const float* __restrict__ bias, float* __restrict__ Cm,
    int M, int N, int K)
{
    extern __shared__ uint32_t smem_u32[];
    uint32_t* const AsBase = smem_u32;          // 2 stages x 4096
    uint32_t* const BsBase = smem_u32 + 8192;   // 2 stages x 4096

    const int tid  = threadIdx.x;
    const int warp = tid >> 5;
    const int lane = tid & 31;
    const int bm = blockIdx.y * 128;
    const int bn = blockIdx.x * 128;

    const int warpM = (warp >> 2) * 64;   // 0 or 64
    const int warpN = (warp & 3) * 32;    // 0,32,64,96
    const int warpMt = (warp >> 2) * 4;   // base mtile
    const int warpNt = (warp & 3) * 4;    // base ntile

    // Global loader mapping
    const int arow = tid >> 1;            // 0..127
    const int akb  = (tid & 1) * 16;      // 0 or 16
    const int brow = tid >> 3;            // 0..31
    const int bcb  = (tid & 7) * 16;      // 0..112

    const float* agp = A + (size_t)(bm + arow) * K + akb;
    const float* bgp = Bm + (size_t)brow * N + bn + bcb;

    // Precompute smem store bases (u32 offsets within a stage)
    int a_base[4], b_base[4];
    {
        const int mt = arow >> 4;
        const int r  = arow & 15;
        const int lanebA = (r & 7) * 4;
        const int ridx = r >> 3;
#pragma unroll
        for (int j = 0; j < 4; j++) {
            const int k = akb + 4 * j;
            const int kc = k >> 3;
            const int aidx = ridx + ((k >> 2) & 1) * 2;
            a_base[j] = ((mt * 4 + kc) * 32 + lanebA) * 4 + aidx;
        }
        const int k = brow;
        const int kc = k >> 3;
        const int bidx = (k >> 2) & 1;
#pragma unroll
        for (int j = 0; j < 4; j++) {
            const int n = bcb + 4 * j;
            const int nt = n >> 3;
            const int lanebB = (n & 7) * 4 + (k & 3);
            b_base[j] = ((nt * 4 + kc) * 32 + lanebB) * 2 + bidx;
        }
    }

    float cacc[4][4][4];
#pragma unroll
    for (int i = 0; i < 4; i++)
#pragma unroll
        for (int j = 0; j < 4; j++)
#pragma unroll
            for (int e = 0; e < 4; e++) cacc[i][j][e] = 0.0f;

    float4 apf[4], bpf[4];

    // Prologue: load + store K-tile 0 into stage 0
#pragma unroll
    for (int j = 0; j < 4; j++) {
        apf[j] = *(const float4*)(agp + 4 * j);
        bpf[j] = *(const float4*)(bgp + (size_t)4 * j);
    }
    agp += 32;
    bgp += (size_t)32 * N;
    {
        uint32_t* As = AsBase;
        uint32_t* Bs = BsBase;
#pragma unroll
        for (int j = 0; j < 4; j++) {
            As[a_base[j] + 0]  = f2tf32(apf[j].x);
            As[a_base[j] + 4]  = f2tf32(apf[j].y);
            As[a_base[j] + 8]  = f2tf32(apf[j].z);
            As[a_base[j] + 12] = f2tf32(apf[j].w);
            Bs[b_base[j] + 0]  = f2tf32(bpf[j].x);
            Bs[b_base[j] + 8]  = f2tf32(bpf[j].y);
            Bs[b_base[j] + 16] = f2tf32(bpf[j].z);
            Bs[b_base[j] + 24] = f2tf32(bpf[j].w);
        }
    }
    __syncthreads();

    const int NT = K >> 5;   // number of 32-wide K-tiles
    for (int t = 0; t < NT; t++) {
        const bool more = (t + 1 < NT);

        // Prefetch next gmem tile (latency hides under MMA block below)
        if (more) {
#pragma unroll
            for (int j = 0; j < 4; j++) {
                apf[j] = *(const float4*)(agp + 4 * j);
                bpf[j] = *(const float4*)(bgp + (size_t)4 * j);
            }
            agp += 32;
            bgp += (size_t)32 * N;
        }

        // MMA over current stage
        {
            const uint32_t* As = AsBase + (t & 1) * 4096;
            const uint32_t* Bs = BsBase + (t & 1) * 4096;
#pragma unroll
            for (int kc = 0; kc < 4; kc++) {
                uint32_t af[4][4];
                uint32_t bf[4][2];
#pragma unroll
                for (int mt4 = 0; mt4 < 4; mt4++) {
                    const int idx = ((warpMt + mt4) * 4 + kc) * 32 + lane;
                    *(uint4*)af[mt4] = *(const uint4*)&As[idx * 4];
                }
#pragma unroll
                for (int nt4 = 0; nt4 < 4; nt4++) {
                    const int idx = ((warpNt + nt4) * 4 + kc) * 32 + lane;
                    *(uint2*)bf[nt4] = *(const uint2*)&Bs[idx * 2];
                }
#pragma unroll
                for (int mt4 = 0; mt4 < 4; mt4++)
#pragma unroll
                    for (int nt4 = 0; nt4 < 4; nt4++)
                        mma_tf32(cacc[mt4][nt4], af[mt4], bf[nt4]);
            }
        }

        // Store prefetched tile into the other stage (overlaps MMA issue)
        if (more) {
            uint32_t* As = AsBase + ((t + 1) & 1) * 4096;
            uint32_t* Bs = BsBase + ((t + 1) & 1) * 4096;
#pragma unroll
            for (int j = 0; j < 4; j++) {
                As[a_base[j] + 0]  = f2tf32(apf[j].x);
                As[a_base[j] + 4]  = f2tf32(apf[j].y);
                As[a_base[j] + 8]  = f2tf32(apf[j].z);
                As[a_base[j] + 12] = f2tf32(apf[j].w);
                Bs[b_base[j] + 0]  = f2tf32(bpf[j].x);
                Bs[b_base[j] + 8]  = f2tf32(bpf[j].y);
                Bs[b_base[j] + 16] = f2tf32(bpf[j].z);
                Bs[b_base[j] + 24] = f2tf32(bpf[j].w);
            }
        }
        __syncthreads();  // single barrier per K-tile
    }

    // Epilogue: C = acc + bias
    const int crow = lane >> 2;
    const int ccol = (lane & 3) * 2;
#pragma unroll
    for (int mt4 = 0; mt4 < 4; mt4++) {
#pragma unroll
        for (int nt4 = 0; nt4 < 4; nt4++) {
            const int grow = bm + warpM + mt4 * 16 + crow;
            const int gcol = bn + warpN + nt4 * 8 + ccol;
            const float b0 = bias[gcol];
            const float b1 = bias[gcol + 1];
            float2 v0, v1;
            v0.x = cacc[mt4][nt4][0] + b0;
            v0.y = cacc[mt4][nt4][1] + b1;
            v1.x = cacc[mt4][nt4][2] + b0;
            v1.y = cacc[mt4][nt4][3] + b1;
            *(float2*)(Cm + (size_t)grow * N + gcol) = v0;
            *(float2*)(Cm + (size_t)(grow + 8) * N + gcol) = v1;
        }
    }
}

// ---------------------------------------------------------------------------
// Flash attention (fp32, online softmax), BQ=64 x BK=32 tiles. (unchanged)
// ---------------------------------------------------------------------------
#define BQ 64
#define BK 32

__global__ void __launch_bounds__(256) attn_kernel(
    const float* __restrict__ kqv, const int* __restrict__ padmask,
    float* __restrict__ y)
{
    __shared__ float Qs[BQ][DD + 1];
    __shared__ float Ks[BK][DD + 1];
    __shared__ float Vs[BK][DD + 1];
    __shared__ float Ps[BQ][BK + 1];
    __shared__ float red[BQ][17];
    __shared__ float m_s[BQ], l_s[BQ], alpha_s[BQ];
    __shared__ int   padv[BK];

    const int q0 = blockIdx.x * BQ;
    const int h  = blockIdx.y;
    const int b  = blockIdx.z;
    const int tid = threadIdx.x;
    const int tr = tid >> 4;
    const int tc = tid & 15;
    const float scale = 0.125f;  // 1/sqrt(64)

    const float* base = kqv + (size_t)b * TT * C3 + (size_t)h * DD;
    const float* qbase = base + CC;       // q segment
    const float* kbase = base;            // k segment
    const float* vbase = base + 2 * CC;   // v segment

    for (int i = tid; i < BQ * (DD / 4); i += 256) {
        int r = i >> 4, c4 = (i & 15) << 2;
        float4 v = *(const float4*)(qbase + (size_t)(q0 + r) * C3 + c4);
        Qs[r][c4 + 0] = v.x; Qs[r][c4 + 1] = v.y;
        Qs[r][c4 + 2] = v.z; Qs[r][c4 + 3] = v.w;
    }
    if (tid < BQ) { m_s[tid] = -1e30f; l_s[tid] = 0.0f; }

    float o[4][4];
#pragma unroll
    for (int i = 0; i < 4; i++)
#pragma unroll
        for (int j = 0; j < 4; j++) o[i][j] = 0.0f;
    __syncthreads();

    const int jend = q0 + BQ;
    for (int j0 = 0; j0 < jend; j0 += BK) {
        for (int i = tid; i < BK * (DD / 4); i += 256) {
            int r = i >> 4, c4 = (i & 15) << 2;
            size_t off = (size_t)(j0 + r) * C3 + c4;
            float4 kv = *(const float4*)(kbase + off);
            float4 vv = *(const float4*)(vbase + off);
            Ks[r][c4 + 0] = kv.x; Ks[r][c4 + 1] = kv.y;
            Ks[r][c4 + 2] = kv.z; Ks[r][c4 + 3] = kv.w;
            Vs[r][c4 + 0] = vv.x; Vs[r][c4 + 1] = vv.y;
            Vs[r][c4 + 2] = vv.z; Vs[r][c4 + 3] = vv.w;
        }
        if (tid < BK) padv[tid] = padmask[b * TT + j0 + tid];
        __syncthreads();

        float s[4][2];
#pragma unroll
        for (int i = 0; i < 4; i++) { s[i][0] = 0.0f; s[i][1] = 0.0f; }
#pragma unroll 8
        for (int d = 0; d < DD; d++) {
            float qv[4], kv[2];
#pragma unroll
            for (int ri = 0; ri < 4; ri++) qv[ri] = Qs[tr * 4 + ri][d];
            kv[0] = Ks[tc * 2 + 0][d];
            kv[1] = Ks[tc * 2 + 1][d];
#pragma unroll
            for (int ri = 0; ri < 4; ri++) {
                s[ri][0] = fmaf(qv[ri], kv[0], s[ri][0]);
                s[ri][1] = fmaf(qv[ri], kv[1], s[ri][1]);
            }
        }

#pragma unroll
        for (int ri = 0; ri < 4; ri++) {
            const int row = tr * 4 + ri;
            const int qi = q0 + row;
            float pm = -1e30f;
#pragma unroll
            for (int ci = 0; ci < 2; ci++) {
                const int col = tc * 2 + ci;
                const int kj = j0 + col;
                const bool valid = (kj <= qi) && (padv[col] != 0);
                float val = valid ? s[ri][ci] * scale : -1e30f;
                Ps[row][col] = val;
                pm = fmaxf(pm, val);
            }
            red[row][tc] = pm;
        }
        __syncthreads();

        if (tid < BQ) {
            float mmax = m_s[tid];
#pragma unroll
            for (int t = 0; t < 16; t++) mmax = fmaxf(mmax, red[tid][t]);
            alpha_s[tid] = __expf(m_s[tid] - mmax);
            m_s[tid] = mmax;
        }
        __syncthreads();

#pragma unroll
        for (int ri = 0; ri < 4; ri++) {
            const int row = tr * 4 + ri;
            const float mrow = m_s[row];
            const float a = alpha_s[row];
            float ps = 0.0f;
#pragma unroll
            for (int ci = 0; ci < 2; ci++) {
                const int col = tc * 2 + ci;
                float p = __expf(Ps[row][col] - mrow);
                Ps[row][col] = p;
                ps += p;
            }
            red[row][tc] = ps;
#pragma unroll
            for (int ci = 0; ci < 4; ci++) o[ri][ci] *= a;
        }
        __syncthreads();

        if (tid < BQ) {
            float sum = 0.0f;
#pragma unroll
            for (int t = 0; t < 16; t++) sum += red[tid][t];
            l_s[tid] = l_s[tid] * alpha_s[tid] + sum;
        }

#pragma unroll 4
        for (int j = 0; j < BK; j++) {
            float pv[4], vv[4];
#pragma unroll
            for (int ri = 0; ri < 4; ri++) pv[ri] = Ps[tr * 4 + ri][j];
#pragma unroll
            for (int ci = 0; ci < 4; ci++) vv[ci] = Vs[j][tc * 4 + ci];
#pragma unroll
            for (int ri = 0; ri < 4; ri++)
#pragma unroll
                for (int ci = 0; ci < 4; ci++)
                    o[ri][ci] = fmaf(pv[ri], vv[ci], o[ri][ci]);
        }
        __syncthreads();
    }

#pragma unroll
    for (int ri = 0; ri < 4; ri++) {
        const int row = tr * 4 + ri;
        const float inv = 1.0f / l_s[row];
        float* yp = y + ((size_t)b * TT + q0 + row) * CC + h * DD + tc * 4;
        float4 v;
        v.x = o[ri][0] * inv; v.y = o[ri][1] * inv;
        v.z = o[ri][2] * inv; v.w = o[ri][3] * inv;
        *(float4*)yp = v;
    }
}

// ---------------------------------------------------------------------------
extern "C" void kernel_launch(void* const* d_in, const int* in_sizes, int n_in,
                              void* d_out, int out_size)
{
    const float* x      = (const float*)d_in[0];
    const float* W_kqv  = (const float*)d_in[1];
    const float* b_kqv  = (const float*)d_in[2];
    const float* W_proj = (const float*)d_in[3];
    const float* b_proj = (const float*)d_in[4];
    const int*   pad    = (const int*)d_in[5];
    float* out = (float*)d_out;

    float* kqv_ptr = nullptr;
    float* y_ptr = nullptr;
    cudaGetSymbolAddress((void**)&kqv_ptr, g_kqv);
    cudaGetSymbolAddress((void**)&y_ptr, g_y);

    const int M = BB * TT;  // 8192
    const int GEMM_SMEM = 2 * (4096 + 4096) * 4;  // 64 KB double-buffered

    cudaFuncSetAttribute(gemm_tf32_bias,
                         cudaFuncAttributeMaxDynamicSharedMemorySize, GEMM_SMEM);

    // 1) kqv = x @ W_kqv + b_kqv   [8192, 3072]
    {
        dim3 grid(C3 / 128, M / 128);
        gemm_tf32_bias<<<grid, 256, GEMM_SMEM>>>(x, W_kqv, b_kqv, kqv_ptr, M, C3, CC);
    }
    // 2) flash attention -> y  [8192, 1024]
    {
        dim3 grid(TT / BQ, HH, BB);
        attn_kernel<<<grid, 256>>>(kqv_ptr, pad, y_ptr);
    }
    // 3) out = y @ W_proj + b_proj  [8192, 1024]
    {
        dim3 grid(CC / 128, M / 128);
        gemm_tf32_bias<<<grid, 256, GEMM_SMEM>>>(y_ptr, W_proj, b_proj, out, M, CC, CC);
    }
}

// round 6
// speedup vs baseline: 2.2249x; 1.3807x over previous
#include <cuda_runtime.h>
#include <cstdint>
#include <cstddef>

// Problem constants
#define BB 4
#define TT 2048
#define CC 1024
#define HH 16
#define DD 64
#define C3 (3 * CC)

// Scratch (allocation-free rule: __device__ globals)
__device__ float g_kqv[(size_t)BB * TT * C3];  // [B,T,3C]  (k | q | v)
__device__ float g_y[(size_t)BB * TT * CC];    // [B,T,C]

__device__ __forceinline__ uint32_t f2tf32(float x) {
    uint32_t r;
    asm("cvt.rna.tf32.f32 %0, %1;" : "=r"(r) : "f"(x));
    return r;
}

__device__ __forceinline__ void mma_tf32(float* d, const uint32_t* a, const uint32_t* b) {
    asm volatile(
        "mma.sync.aligned.m16n8k8.row.col.f32.tf32.tf32.f32 "
        "{%0,%1,%2,%3}, {%4,%5,%6,%7}, {%8,%9}, {%0,%1,%2,%3};"
        : "+f"(d[0]), "+f"(d[1]), "+f"(d[2]), "+f"(d[3])
        : "r"(a[0]), "r"(a[1]), "r"(a[2]), "r"(a[3]), "r"(b[0]), "r"(b[1]));
}

// ---------------------------------------------------------------------------
// TF32 tensor-core GEMM with bias (unchanged from R5: double-buffered)
// ---------------------------------------------------------------------------
__global__ void __launch_bounds__(256, 2) gemm_tf32_bias(
    const float* __restrict__ A, const float* __restrict__ Bm,
    const float* __restrict__ bias, float* __restrict__ Cm,
    int M, int N, int K)
{
    extern __shared__ uint32_t smem_u32[];
    uint32_t* const AsBase = smem_u32;          // 2 stages x 4096
    uint32_t* const BsBase = smem_u32 + 8192;   // 2 stages x 4096

    const int tid  = threadIdx.x;
    const int warp = tid >> 5;
    const int lane = tid & 31;
    const int bm = blockIdx.y * 128;
    const int bn = blockIdx.x * 128;

    const int warpM = (warp >> 2) * 64;
    const int warpN = (warp & 3) * 32;
    const int warpMt = (warp >> 2) * 4;
    const int warpNt = (warp & 3) * 4;

    const int arow = tid >> 1;
    const int akb  = (tid & 1) * 16;
    const int brow = tid >> 3;
    const int bcb  = (tid & 7) * 16;

    const float* agp = A + (size_t)(bm + arow) * K + akb;
    const float* bgp = Bm + (size_t)brow * N + bn + bcb;

    int a_base[4], b_base[4];
    {
        const int mt = arow >> 4;
        const int r  = arow & 15;
        const int lanebA = (r & 7) * 4;
        const int ridx = r >> 3;
#pragma unroll
        for (int j = 0; j < 4; j++) {
            const int k = akb + 4 * j;
            const int kc = k >> 3;
            const int aidx = ridx + ((k >> 2) & 1) * 2;
            a_base[j] = ((mt * 4 + kc) * 32 + lanebA) * 4 + aidx;
        }
        const int k = brow;
        const int kc = k >> 3;
        const int bidx = (k >> 2) & 1;
#pragma unroll
        for (int j = 0; j < 4; j++) {
            const int n = bcb + 4 * j;
            const int nt = n >> 3;
            const int lanebB = (n & 7) * 4 + (k & 3);
            b_base[j] = ((nt * 4 + kc) * 32 + lanebB) * 2 + bidx;
        }
    }

    float cacc[4][4][4];
#pragma unroll
    for (int i = 0; i < 4; i++)
#pragma unroll
        for (int j = 0; j < 4; j++)
#pragma unroll
            for (int e = 0; e < 4; e++) cacc[i][j][e] = 0.0f;

    float4 apf[4], bpf[4];
#pragma unroll
    for (int j = 0; j < 4; j++) {
        apf[j] = *(const float4*)(agp + 4 * j);
        bpf[j] = *(const float4*)(bgp + (size_t)4 * j);
    }
    agp += 32;
    bgp += (size_t)32 * N;
    {
        uint32_t* As = AsBase;
        uint32_t* Bs = BsBase;
#pragma unroll
        for (int j = 0; j < 4; j++) {
            As[a_base[j] + 0]  = f2tf32(apf[j].x);
            As[a_base[j] + 4]  = f2tf32(apf[j].y);
            As[a_base[j] + 8]  = f2tf32(apf[j].z);
            As[a_base[j] + 12] = f2tf32(apf[j].w);
            Bs[b_base[j] + 0]  = f2tf32(bpf[j].x);
            Bs[b_base[j] + 8]  = f2tf32(bpf[j].y);
            Bs[b_base[j] + 16] = f2tf32(bpf[j].z);
            Bs[b_base[j] + 24] = f2tf32(bpf[j].w);
        }
    }
    __syncthreads();

    const int NT = K >> 5;
    for (int t = 0; t < NT; t++) {
        const bool more = (t + 1 < NT);
        if (more) {
#pragma unroll
            for (int j = 0; j < 4; j++) {
                apf[j] = *(const float4*)(agp + 4 * j);
                bpf[j] = *(const float4*)(bgp + (size_t)4 * j);
            }
            agp += 32;
            bgp += (size_t)32 * N;
        }
        {
            const uint32_t* As = AsBase + (t & 1) * 4096;
            const uint32_t* Bs = BsBase + (t & 1) * 4096;
#pragma unroll
            for (int kc = 0; kc < 4; kc++) {
                uint32_t af[4][4];
                uint32_t bf[4][2];
#pragma unroll
                for (int mt4 = 0; mt4 < 4; mt4++) {
                    const int idx = ((warpMt + mt4) * 4 + kc) * 32 + lane;
                    *(uint4*)af[mt4] = *(const uint4*)&As[idx * 4];
                }
#pragma unroll
                for (int nt4 = 0; nt4 < 4; nt4++) {
                    const int idx = ((warpNt + nt4) * 4 + kc) * 32 + lane;
                    *(uint2*)bf[nt4] = *(const uint2*)&Bs[idx * 2];
                }
#pragma unroll
                for (int mt4 = 0; mt4 < 4; mt4++)
#pragma unroll
                    for (int nt4 = 0; nt4 < 4; nt4++)
                        mma_tf32(cacc[mt4][nt4], af[mt4], bf[nt4]);
            }
        }
        if (more) {
            uint32_t* As = AsBase + ((t + 1) & 1) * 4096;
            uint32_t* Bs = BsBase + ((t + 1) & 1) * 4096;
#pragma unroll
            for (int j = 0; j < 4; j++) {
                As[a_base[j] + 0]  = f2tf32(apf[j].x);
                As[a_base[j] + 4]  = f2tf32(apf[j].y);
                As[a_base[j] + 8]  = f2tf32(apf[j].z);
                As[a_base[j] + 12] = f2tf32(apf[j].w);
                Bs[b_base[j] + 0]  = f2tf32(bpf[j].x);
                Bs[b_base[j] + 8]  = f2tf32(bpf[j].y);
                Bs[b_base[j] + 16] = f2tf32(bpf[j].z);
                Bs[b_base[j] + 24] = f2tf32(bpf[j].w);
            }
        }
        __syncthreads();
    }

    const int crow = lane >> 2;
    const int ccol = (lane & 3) * 2;
#pragma unroll
    for (int mt4 = 0; mt4 < 4; mt4++) {
#pragma unroll
        for (int nt4 = 0; nt4 < 4; nt4++) {
            const int grow = bm + warpM + mt4 * 16 + crow;
            const int gcol = bn + warpN + nt4 * 8 + ccol;
            const float b0 = bias[gcol];
            const float b1 = bias[gcol + 1];
            float2 v0, v1;
            v0.x = cacc[mt4][nt4][0] + b0;
            v0.y = cacc[mt4][nt4][1] + b1;
            v1.x = cacc[mt4][nt4][2] + b0;
            v1.y = cacc[mt4][nt4][3] + b1;
            *(float2*)(Cm + (size_t)grow * N + gcol) = v0;
            *(float2*)(Cm + (size_t)(grow + 8) * N + gcol) = v1;
        }
    }
}

// ---------------------------------------------------------------------------
// Flash attention, TF32 tensor-core S=QK^T and O+=PV, scalar online softmax.
// BQ=64 queries x BK=32 keys per tile, 256 threads (8 warps).
// S warp map: warp w -> rows [16*(w>>1)..+15], col-tiles nt in {(w&1)*2, +1}.
// O warp map: warp w -> rows [16*(w>>1)..+15], cols [(w&1)*32 .. +31] (nt 0..3).
// Fragment smem:
//   Qf: [mt4][kc8][lane32][4]  (tf32)   Kf: [nt4][kc8][lane32][2]
//   Vf: [nt8][kc4][lane32][2]  (k-dim = key index j)
// ---------------------------------------------------------------------------
#define BQ 64
#define BK 32
#define PSTR 36   // Ps row stride (floats): (r*36+c)&31 = (4r+c)&31 -> conflict-free frags

__global__ void __launch_bounds__(256) attn_kernel(
    const float* __restrict__ kqv, const int* __restrict__ padmask,
    float* __restrict__ y)
{
    __shared__ uint32_t Qf[4096];
    __shared__ uint32_t Kf[2048];
    __shared__ uint32_t Vf[2048];
    __shared__ float Ps[BQ * PSTR];
    __shared__ float red[BQ][4];
    __shared__ float m_s[BQ], l_s[BQ], alpha_s[BQ];
    __shared__ int   padv[BK];

    const int q0 = blockIdx.x * BQ;
    const int h  = blockIdx.y;
    const int b  = blockIdx.z;
    const int tid = threadIdx.x;
    const int warp = tid >> 5;
    const int lane = tid & 31;
    const float scale = 0.125f;  // 1/sqrt(64)

    const float* base  = kqv + (size_t)b * TT * C3 + (size_t)h * DD;
    const float* qbase = base + CC;
    const float* kbase = base;
    const float* vbase = base + 2 * CC;

    // ---- Load Q tile (64x64) into fragment-ordered smem (tf32) ----
    {
        const int r  = tid >> 2;            // 0..63
        const int kb = (tid & 3) * 16;      // 0,16,32,48
        const float* qp = qbase + (size_t)(q0 + r) * C3 + kb;
        const int mt = r >> 4;
        const int rr = r & 15;
        const int laneb = (rr & 7) * 4;
        const int ridx = rr >> 3;
#pragma unroll
        for (int j = 0; j < 4; j++) {
            float4 v = *(const float4*)(qp + 4 * j);
            const int k = kb + 4 * j;
            const int kc = k >> 3;
            const int reg = ridx + ((k >> 2) & 1) * 2;
            uint32_t* dst = &Qf[((mt * 8 + kc) * 32 + laneb) * 4 + reg];
            dst[0]  = f2tf32(v.x);
            dst[4]  = f2tf32(v.y);
            dst[8]  = f2tf32(v.z);
            dst[12] = f2tf32(v.w);
        }
    }
    if (tid < BQ) { m_s[tid] = -1e30f; l_s[tid] = 0.0f; }
    __syncthreads();

    // Q A-fragments held in registers for the whole block
    const int mtw = warp >> 1;          // S/O row group
    const int ntb = (warp & 1) * 2;     // S col-tile base
    uint32_t aq[8][4];
#pragma unroll
    for (int kc = 0; kc < 8; kc++)
        *(uint4*)aq[kc] = *(const uint4*)&Qf[((mtw * 8 + kc) * 32 + lane) * 4];

    const int r0 = mtw * 16 + (lane >> 2);   // fragment row 0 (rows of S and O)
    const int r1 = r0 + 8;

    float oacc[4][4];
#pragma unroll
    for (int i = 0; i < 4; i++)
#pragma unroll
        for (int e = 0; e < 4; e++) oacc[i][e] = 0.0f;

    const int jend = q0 + BQ;
    for (int j0 = 0; j0 < jend; j0 += BK) {
        __syncthreads();  // prev tile's PV reads done before overwrite

        // ---- Load K,V tiles (32x64) fragment-ordered (tf32) + padmask ----
        {
            const int jr = tid >> 3;            // 0..31
            const int db = (tid & 7) * 8;       // 0..56
            const size_t off = (size_t)(j0 + jr) * C3 + db;
            float4 k0 = *(const float4*)(kbase + off);
            float4 k1 = *(const float4*)(kbase + off + 4);
            float4 v0 = *(const float4*)(vbase + off);
            float4 v1 = *(const float4*)(vbase + off + 4);

            // K: nt=jr>>3, kc=db>>3=tid&7, lane=(jr&7)*4 + (d&3), reg=(d>>2)&1
            {
                const int nt = jr >> 3;
                const int kc = tid & 7;
                uint32_t* dst = &Kf[((nt * 8 + kc) * 32 + (jr & 7) * 4) * 2];
                dst[0] = f2tf32(k0.x); dst[2] = f2tf32(k0.y);
                dst[4] = f2tf32(k0.z); dst[6] = f2tf32(k0.w);
                dst[1] = f2tf32(k1.x); dst[3] = f2tf32(k1.y);
                dst[5] = f2tf32(k1.z); dst[7] = f2tf32(k1.w);
            }
            // V: nt=d>>3=tid&7, kc=jr>>3, lane=(d&7)*4 + (jr&3), reg=(jr>>2)&1
            {
                const int nt = tid & 7;
                const int kc = jr >> 3;
                const int reg = (jr >> 2) & 1;
                uint32_t* dst = &Vf[((nt * 4 + kc) * 32 + (jr & 3)) * 2 + reg];
                dst[0]  = f2tf32(v0.x); dst[8]  = f2tf32(v0.y);
                dst[16] = f2tf32(v0.z); dst[24] = f2tf32(v0.w);
                dst[32] = f2tf32(v1.x); dst[40] = f2tf32(v1.y);
                dst[48] = f2tf32(v1.z); dst[56] = f2tf32(v1.w);
            }
        }
        if (tid < BK) padv[tid] = padmask[b * TT + j0 + tid];
        __syncthreads();

        // ---- S = Q @ K^T via MMA ----
        float sacc[2][4];
#pragma unroll
        for (int i = 0; i < 2; i++)
#pragma unroll
            for (int e = 0; e < 4; e++) sacc[i][e] = 0.0f;
#pragma unroll
        for (int kc = 0; kc < 8; kc++) {
#pragma unroll
            for (int i = 0; i < 2; i++) {
                uint32_t bf[2];
                *(uint2*)bf = *(const uint2*)&Kf[(((ntb + i) * 8 + kc) * 32 + lane) * 2];
                mma_tf32(sacc[i], aq[kc], bf);
            }
        }

        // ---- Scale + mask, store to Ps ----
#pragma unroll
        for (int i = 0; i < 2; i++) {
            const int cb = (ntb + i) * 8 + 2 * (lane & 3);
#pragma unroll
            for (int e = 0; e < 2; e++) {
                const int col = cb + e;
                const int kj = j0 + col;
                const bool pv = (padv[col] != 0);
                Ps[r0 * PSTR + col] = (pv && kj <= q0 + r0) ? sacc[i][e] * scale : -1e30f;
                Ps[r1 * PSTR + col] = (pv && kj <= q0 + r1) ? sacc[i][2 + e] * scale : -1e30f;
            }
        }
        __syncthreads();

        // ---- Row max partials ----
        {
            const int row = tid >> 2;
            const int cb = (tid & 3) * 8;
            float pm = -1e30f;
#pragma unroll
            for (int e = 0; e < 8; e++) pm = fmaxf(pm, Ps[row * PSTR + cb + e]);
            red[row][tid & 3] = pm;
        }
        __syncthreads();

        if (tid < BQ) {
            float m = m_s[tid];
            m = fmaxf(m, red[tid][0]); m = fmaxf(m, red[tid][1]);
            m = fmaxf(m, red[tid][2]); m = fmaxf(m, red[tid][3]);
            alpha_s[tid] = __expf(m_s[tid] - m);
            m_s[tid] = m;
        }
        __syncthreads();

        // ---- Rescale O fragments ----
        {
            const float a0 = alpha_s[r0];
            const float a1 = alpha_s[r1];
#pragma unroll
            for (int nt = 0; nt < 4; nt++) {
                oacc[nt][0] *= a0; oacc[nt][1] *= a0;
                oacc[nt][2] *= a1; oacc[nt][3] *= a1;
            }
        }
        // ---- exp + row-sum partials ----
        {
            const int row = tid >> 2;
            const int cb = (tid & 3) * 8;
            const float mr = m_s[row];
            float ps = 0.0f;
#pragma unroll
            for (int e = 0; e < 8; e++) {
                float p = __expf(Ps[row * PSTR + cb + e] - mr);
                Ps[row * PSTR + cb + e] = p;
                ps += p;
            }
            red[row][tid & 3] = ps;
        }
        __syncthreads();

        if (tid < BQ)
            l_s[tid] = l_s[tid] * alpha_s[tid]
                     + red[tid][0] + red[tid][1] + red[tid][2] + red[tid][3];

        // ---- O += P @ V via MMA ----
#pragma unroll
        for (int kc = 0; kc < 4; kc++) {
            const int pc = kc * 8 + (lane & 3);
            uint32_t ap[4];
            ap[0] = f2tf32(Ps[r0 * PSTR + pc]);
            ap[1] = f2tf32(Ps[r1 * PSTR + pc]);
            ap[2] = f2tf32(Ps[r0 * PSTR + pc + 4]);
            ap[3] = f2tf32(Ps[r1 * PSTR + pc + 4]);
#pragma unroll
            for (int nt = 0; nt < 4; nt++) {
                const int ntg = (warp & 1) * 4 + nt;
                uint32_t bv[2];
                *(uint2*)bv = *(const uint2*)&Vf[((ntg * 4 + kc) * 32 + lane) * 2];
                mma_tf32(oacc[nt], ap, bv);
            }
        }
    }
    __syncthreads();  // l_s final before epilogue

    // ---- Epilogue: normalize + store ----
    {
        const float inv0 = 1.0f / l_s[r0];
        const float inv1 = 1.0f / l_s[r1];
        float* y0 = y + ((size_t)b * TT + q0 + r0) * CC + h * DD;
        float* y1 = y + ((size_t)b * TT + q0 + r1) * CC + h * DD;
#pragma unroll
        for (int nt = 0; nt < 4; nt++) {
            const int c = (warp & 1) * 32 + nt * 8 + 2 * (lane & 3);
            float2 v0, v1;
            v0.x = oacc[nt][0] * inv0; v0.y = oacc[nt][1] * inv0;
            v1.x = oacc[nt][2] * inv1; v1.y = oacc[nt][3] * inv1;
            *(float2*)(y0 + c) = v0;
            *(float2*)(y1 + c) = v1;
        }
    }
}

// ---------------------------------------------------------------------------
extern "C" void kernel_launch(void* const* d_in, const int* in_sizes, int n_in,
                              void* d_out, int out_size)
{
    const float* x      = (const float*)d_in[0];
    const float* W_kqv  = (const float*)d_in[1];
    const float* b_kqv  = (const float*)d_in[2];
    const float* W_proj = (const float*)d_in[3];
    const float* b_proj = (const float*)d_in[4];
    const int*   pad    = (const int*)d_in[5];
    float* out = (float*)d_out;

    float* kqv_ptr = nullptr;
    float* y_ptr = nullptr;
    cudaGetSymbolAddress((void**)&kqv_ptr, g_kqv);
    cudaGetSymbolAddress((void**)&y_ptr, g_y);

    const int M = BB * TT;  // 8192
    const int GEMM_SMEM = 2 * (4096 + 4096) * 4;  // 64 KB double-buffered

    cudaFuncSetAttribute(gemm_tf32_bias,
                         cudaFuncAttributeMaxDynamicSharedMemorySize, GEMM_SMEM);

    // 1) kqv = x @ W_kqv + b_kqv   [8192, 3072]
    {
        dim3 grid(C3 / 128, M / 128);
        gemm_tf32_bias<<<grid, 256, GEMM_SMEM>>>(x, W_kqv, b_kqv, kqv_ptr, M, C3, CC);
    }
    // 2) flash attention -> y  [8192, 1024]
    {
        dim3 grid(TT / BQ, HH, BB);
        attn_kernel<<<grid, 256>>>(kqv_ptr, pad, y_ptr);
    }
    // 3) out = y @ W_proj + b_proj  [8192, 1024]
    {
        dim3 grid(CC / 128, M / 128);
        gemm_tf32_bias<<<grid, 256, GEMM_SMEM>>>(y_ptr, W_proj, b_proj, out, M, CC, CC);
    }
}

// round 8
// speedup vs baseline: 3.1888x; 1.4332x over previous
#include <cuda_runtime.h>
#include <cstdint>
#include <cstddef>

// Problem constants
#define BB 4
#define TT 2048
#define CC 1024
#define HH 16
#define DD 64
#define C3 (3 * CC)
#define GK 1024   // K of both dense GEMMs

// Scratch (allocation-free rule: __device__ globals)
__device__ float g_kqv[(size_t)BB * TT * C3];   // [B,T,3C]  (k | q | v)
__device__ float g_y[(size_t)BB * TT * CC];     // [B,T,C]   (tf32-rounded)
__device__ float g_xr[(size_t)BB * TT * CC];    // x rounded to tf32
__device__ float g_wk[(size_t)CC * C3];         // W_kqv rounded, natural [K,N]
__device__ float g_wp[(size_t)CC * CC];         // W_proj rounded, natural [K,N]

// ---------------------------------------------------------------------------
// Helpers
// ---------------------------------------------------------------------------
__device__ __forceinline__ uint32_t f2tf32(float x) {
    uint32_t r;
    asm("cvt.rna.tf32.f32 %0, %1;" : "=r"(r) : "f"(x));
    return r;
}

__device__ __forceinline__ void mma_tf32(float* d, const uint32_t* a, const uint32_t* b) {
    asm volatile(
        "mma.sync.aligned.m16n8k8.row.col.f32.tf32.tf32.f32 "
        "{%0,%1,%2,%3}, {%4,%5,%6,%7}, {%8,%9}, {%0,%1,%2,%3};"
        : "+f"(d[0]), "+f"(d[1]), "+f"(d[2]), "+f"(d[3])
        : "r"(a[0]), "r"(a[1]), "r"(a[2]), "r"(a[3]), "r"(b[0]), "r"(b[1]));
}

__device__ __forceinline__ uint32_t smem_u32(const void* p) {
    return (uint32_t)__cvta_generic_to_shared(p);
}
__device__ __forceinline__ void cp16(uint32_t s, const void* g) {
    asm volatile("cp.async.cg.shared.global [%0], [%1], 16;" :: "r"(s), "l"(g));
}
__device__ __forceinline__ void cp_commit() {
    asm volatile("cp.async.commit_group;" ::: "memory");
}
template <int n>
__device__ __forceinline__ void cp_wait() {
    asm volatile("cp.async.wait_group %0;" :: "n"(n) : "memory");
}
__device__ __forceinline__ uint32_t lds32(uint32_t a) {
    uint32_t v;
    asm volatile("ld.shared.b32 %0, [%1];" : "=r"(v) : "r"(a));
    return v;
}

#define SWZ128(o) ((o) ^ (((o) >> 3) & 0x70))

// ---------------------------------------------------------------------------
// Prep: tf32 rounding copy (1024 floats per block)
// ---------------------------------------------------------------------------
__global__ void round_copy(const float* __restrict__ in, float* __restrict__ out) {
    const int i = (blockIdx.x * 256 + threadIdx.x) * 4;
    float4 v = *(const float4*)(in + i);
    v.x = __uint_as_float(f2tf32(v.x));
    v.y = __uint_as_float(f2tf32(v.y));
    v.z = __uint_as_float(f2tf32(v.z));
    v.w = __uint_as_float(f2tf32(v.w));
    *(float4*)(out + i) = v;
}

// ---------------------------------------------------------------------------
// TF32 mma.sync GEMM with bias: C[M,N] = A[M,1024] @ B[1024,N] + bias[N]
// CTA tile 128x256, BK=32, 256 threads (8 warps), warp tile 64x64.
// cp.async double-buffered smem, natural layouts + XOR swizzle, LDS.32 frags.
// A, B pre-rounded to tf32. Requires M%128==0, N%256==0.
// smem: A stages 2x16KB @ 0, B stages 2x32KB @ 32768.  Total 96KB.
// ---------------------------------------------------------------------------
#define SMA(s) ((s) * 16384)
#define SMB(s) (32768 + (s) * 32768)
#define GSMEM  98304

__device__ __forceinline__ void gemm_copy_tile(
    uint32_t sb, int s, const float* __restrict__ A, const float* __restrict__ B,
    int bm, int bn, int k0, int N, int tid)
{
    // A: 128 rows x 32 floats (128B rows), SW128 swizzle
#pragma unroll
    for (int i = 0; i < 4; i++) {
        const int g = tid + i * 256;
        const int row = g >> 3;
        const int c16 = g & 7;
        const uint32_t so = sb + SMA(s) + SWZ128((uint32_t)(row * 128 + c16 * 16));
        cp16(so, A + (size_t)(bm + row) * GK + k0 + c16 * 4);
    }
    // B: 32 k-rows x 256 floats (1KB rows), granule swizzle c16 ^= (k&3)<<1
#pragma unroll
    for (int i = 0; i < 8; i++) {
        const int g = tid + i * 256;
        const int k = g >> 6;
        const int c16 = g & 63;
        const uint32_t so = sb + SMB(s) + k * 1024 + ((c16 ^ ((k & 3) << 1)) << 4);
        cp16(so, B + (size_t)(k0 + k) * N + bn + c16 * 4);
    }
}

__global__ void __launch_bounds__(256, 1) gemm_tf32_bias(
    const float* __restrict__ A, const float* __restrict__ Bm,
    const float* __restrict__ bias, float* __restrict__ Cm, int N)
{
    extern __shared__ char smem[];
    const uint32_t sb = smem_u32(smem);
    const int tid  = threadIdx.x;
    const int warp = tid >> 5;
    const int lane = tid & 31;
    const int bm = blockIdx.y * 128;
    const int bn = blockIdx.x * 256;

    const int warpM = (warp >> 2) * 64;   // 0 or 64
    const int warpN = (warp & 3) * 64;    // 0,64,128,192

    float acc[4][8][4];
#pragma unroll
    for (int i = 0; i < 4; i++)
#pragma unroll
        for (int j = 0; j < 8; j++)
#pragma unroll
            for (int e = 0; e < 4; e++) acc[i][j][e] = 0.0f;

    // Prologue: fill both stages
    gemm_copy_tile(sb, 0, A, Bm, bm, bn, 0, N, tid);
    cp_commit();
    gemm_copy_tile(sb, 1, A, Bm, bm, bn, 32, N, tid);
    cp_commit();

    const int lc = lane & 3;     // k low bits / frag col
    const int lr = lane >> 2;    // frag row

    const int NT = GK / 32;  // 32
    for (int t = 0; t < NT; t++) {
        const int s = t & 1;
        cp_wait<1>();
        __syncthreads();

        const uint32_t aBase = sb + SMA(s);
        const uint32_t bBase = sb + SMB(s);
#pragma unroll
        for (int kc = 0; kc < 4; kc++) {
            uint32_t af[4][4];
#pragma unroll
            for (int mt = 0; mt < 4; mt++) {
                const int r0 = warpM + mt * 16 + lr;
                const int cb = (kc * 8 + lc) * 4;
                af[mt][0] = lds32(aBase + SWZ128((uint32_t)(r0 * 128 + cb)));
                af[mt][1] = lds32(aBase + SWZ128((uint32_t)((r0 + 8) * 128 + cb)));
                af[mt][2] = lds32(aBase + SWZ128((uint32_t)(r0 * 128 + cb + 16)));
                af[mt][3] = lds32(aBase + SWZ128((uint32_t)((r0 + 8) * 128 + cb + 16)));
            }
            uint32_t bf[8][2];
#pragma unroll
            for (int nt = 0; nt < 8; nt++) {
                const int n = warpN + nt * 8 + lr;
                const int k = kc * 8 + lc;
                const uint32_t swz = (uint32_t)(((n >> 2) ^ (lc << 1)) << 4) + ((n & 3) << 2);
                bf[nt][0] = lds32(bBase + k * 1024 + swz);
                bf[nt][1] = lds32(bBase + (k + 4) * 1024 + swz);
            }
#pragma unroll
            for (int mt = 0; mt < 4; mt++)
#pragma unroll
                for (int nt = 0; nt < 8; nt++)
                    mma_tf32(acc[mt][nt], af[mt], bf[nt]);
        }
        __syncthreads();

        if (t + 2 < NT) {
            gemm_copy_tile(sb, s, A, Bm, bm, bn, (t + 2) * 32, N, tid);
            cp_commit();
        }
    }

    // Epilogue: C = acc + bias
    const int r = lr, c2 = lc * 2;
#pragma unroll
    for (int mt = 0; mt < 4; mt++) {
#pragma unroll
        for (int nt = 0; nt < 8; nt++) {
            const int grow = bm + warpM + mt * 16 + r;
            const int gcol = bn + warpN + nt * 8 + c2;
            const float b0 = bias[gcol];
            const float b1 = bias[gcol + 1];
            float2 v0, v1;
            v0.x = acc[mt][nt][0] + b0;
            v0.y = acc[mt][nt][1] + b1;
            v1.x = acc[mt][nt][2] + b0;
            v1.y = acc[mt][nt][3] + b1;
            *(float2*)(Cm + (size_t)grow * N + gcol) = v0;
            *(float2*)(Cm + (size_t)(grow + 8) * N + gcol) = v1;
        }
    }
}

// ---------------------------------------------------------------------------
// Flash attention, TF32 mma.sync S=QK^T and O+=PV, scalar online softmax.
// (R6 kernel, validated; epilogue stores tf32-rounded y)
// ---------------------------------------------------------------------------
#define BQ 64
#define BK 32
#define PSTR 36

__global__ void __launch_bounds__(256) attn_kernel(
    const float* __restrict__ kqv, const int* __restrict__ padmask,
    float* __restrict__ y)
{
    __shared__ uint32_t Qf[4096];
    __shared__ uint32_t Kf[2048];
    __shared__ uint32_t Vf[2048];
    __shared__ float Ps[BQ * PSTR];
    __shared__ float red[BQ][4];
    __shared__ float m_s[BQ], l_s[BQ], alpha_s[BQ];
    __shared__ int   padv[BK];

    const int q0 = blockIdx.x * BQ;
    const int h  = blockIdx.y;
    const int b  = blockIdx.z;
    const int tid = threadIdx.x;
    const int warp = tid >> 5;
    const int lane = tid & 31;
    const float scale = 0.125f;

    const float* base  = kqv + (size_t)b * TT * C3 + (size_t)h * DD;
    const float* qbase = base + CC;
    const float* kbase = base;
    const float* vbase = base + 2 * CC;

    {
        const int r  = tid >> 2;
        const int kb = (tid & 3) * 16;
        const float* qp = qbase + (size_t)(q0 + r) * C3 + kb;
        const int mt = r >> 4;
        const int rr = r & 15;
        const int laneb = (rr & 7) * 4;
        const int ridx = rr >> 3;
#pragma unroll
        for (int j = 0; j < 4; j++) {
            float4 v = *(const float4*)(qp + 4 * j);
            const int k = kb + 4 * j;
            const int kc = k >> 3;
            const int reg = ridx + ((k >> 2) & 1) * 2;
            uint32_t* dst = &Qf[((mt * 8 + kc) * 32 + laneb) * 4 + reg];
            dst[0]  = f2tf32(v.x);
            dst[4]  = f2tf32(v.y);
            dst[8]  = f2tf32(v.z);
            dst[12] = f2tf32(v.w);
        }
    }
    if (tid < BQ) { m_s[tid] = -1e30f; l_s[tid] = 0.0f; }
    __syncthreads();

    const int mtw = warp >> 1;
    const int ntb = (warp & 1) * 2;
    uint32_t aq[8][4];
#pragma unroll
    for (int kc = 0; kc < 8; kc++)
        *(uint4*)aq[kc] = *(const uint4*)&Qf[((mtw * 8 + kc) * 32 + lane) * 4];

    const int r0 = mtw * 16 + (lane >> 2);
    const int r1 = r0 + 8;

    float oacc[4][4];
#pragma unroll
    for (int i = 0; i < 4; i++)
#pragma unroll
        for (int e = 0; e < 4; e++) oacc[i][e] = 0.0f;

    const int jend = q0 + BQ;
    for (int j0 = 0; j0 < jend; j0 += BK) {
        __syncthreads();

        {
            const int jr = tid >> 3;
            const int db = (tid & 7) * 8;
            const size_t off = (size_t)(j0 + jr) * C3 + db;
            float4 k0 = *(const float4*)(kbase + off);
            float4 k1 = *(const float4*)(kbase + off + 4);
            float4 v0 = *(const float4*)(vbase + off);
            float4 v1 = *(const float4*)(vbase + off + 4);
            {
                const int nt = jr >> 3;
                const int kc = tid & 7;
                uint32_t* dst = &Kf[((nt * 8 + kc) * 32 + (jr & 7) * 4) * 2];
                dst[0] = f2tf32(k0.x); dst[2] = f2tf32(k0.y);
                dst[4] = f2tf32(k0.z); dst[6] = f2tf32(k0.w);
                dst[1] = f2tf32(k1.x); dst[3] = f2tf32(k1.y);
                dst[5] = f2tf32(k1.z); dst[7] = f2tf32(k1.w);
            }
            {
                const int nt = tid & 7;
                const int kc = jr >> 3;
                const int reg = (jr >> 2) & 1;
                uint32_t* dst = &Vf[((nt * 4 + kc) * 32 + (jr & 3)) * 2 + reg];
                dst[0]  = f2tf32(v0.x); dst[8]  = f2tf32(v0.y);
                dst[16] = f2tf32(v0.z); dst[24] = f2tf32(v0.w);
                dst[32] = f2tf32(v1.x); dst[40] = f2tf32(v1.y);
                dst[48] = f2tf32(v1.z); dst[56] = f2tf32(v1.w);
            }
        }
        if (tid < BK) padv[tid] = padmask[b * TT + j0 + tid];
        __syncthreads();

        float sacc[2][4];
#pragma unroll
        for (int i = 0; i < 2; i++)
#pragma unroll
            for (int e = 0; e < 4; e++) sacc[i][e] = 0.0f;
#pragma unroll
        for (int kc = 0; kc < 8; kc++) {
#pragma unroll
            for (int i = 0; i < 2; i++) {
                uint32_t bf[2];
                *(uint2*)bf = *(const uint2*)&Kf[(((ntb + i) * 8 + kc) * 32 + lane) * 2];
                mma_tf32(sacc[i], aq[kc], bf);
            }
        }

#pragma unroll
        for (int i = 0; i < 2; i++) {
            const int cb = (ntb + i) * 8 + 2 * (lane & 3);
#pragma unroll
            for (int e = 0; e < 2; e++) {
                const int col = cb + e;
                const int kj = j0 + col;
                const bool pv = (padv[col] != 0);
                Ps[r0 * PSTR + col] = (pv && kj <= q0 + r0) ? sacc[i][e] * scale : -1e30f;
                Ps[r1 * PSTR + col] = (pv && kj <= q0 + r1) ? sacc[i][2 + e] * scale : -1e30f;
            }
        }
        __syncthreads();

        {
            const int row = tid >> 2;
            const int cb = (tid & 3) * 8;
            float pm = -1e30f;
#pragma unroll
            for (int e = 0; e < 8; e++) pm = fmaxf(pm, Ps[row * PSTR + cb + e]);
            red[row][tid & 3] = pm;
        }
        __syncthreads();

        if (tid < BQ) {
            float m = m_s[tid];
            m = fmaxf(m, red[tid][0]); m = fmaxf(m, red[tid][1]);
            m = fmaxf(m, red[tid][2]); m = fmaxf(m, red[tid][3]);
            alpha_s[tid] = __expf(m_s[tid] - m);
            m_s[tid] = m;
        }
        __syncthreads();

        {
            const float a0 = alpha_s[r0];
            const float a1 = alpha_s[r1];
#pragma unroll
            for (int nt = 0; nt < 4; nt++) {
                oacc[nt][0] *= a0; oacc[nt][1] *= a0;
                oacc[nt][2] *= a1; oacc[nt][3] *= a1;
            }
        }
        {
            const int row = tid >> 2;
            const int cb = (tid & 3) * 8;
            const float mr = m_s[row];
            float ps = 0.0f;
#pragma unroll
            for (int e = 0; e < 8; e++) {
                float p = __expf(Ps[row * PSTR + cb + e] - mr);
                Ps[row * PSTR + cb + e] = p;
                ps += p;
            }
            red[row][tid & 3] = ps;
        }
        __syncthreads();

        if (tid < BQ)
            l_s[tid] = l_s[tid] * alpha_s[tid]
                     + red[tid][0] + red[tid][1] + red[tid][2] + red[tid][3];

#pragma unroll
        for (int kc = 0; kc < 4; kc++) {
            const int pc = kc * 8 + (lane & 3);
            uint32_t ap[4];
            ap[0] = f2tf32(Ps[r0 * PSTR + pc]);
            ap[1] = f2tf32(Ps[r1 * PSTR + pc]);
            ap[2] = f2tf32(Ps[r0 * PSTR + pc + 4]);
            ap[3] = f2tf32(Ps[r1 * PSTR + pc + 4]);
#pragma unroll
            for (int nt = 0; nt < 4; nt++) {
                const int ntg = (warp & 1) * 4 + nt;
                uint32_t bv[2];
                *(uint2*)bv = *(const uint2*)&Vf[((ntg * 4 + kc) * 32 + lane) * 2];
                mma_tf32(oacc[nt], ap, bv);
            }
        }
    }
    __syncthreads();

    // Epilogue: normalize + store y, pre-rounded to tf32 for the proj GEMM
    {
        const float inv0 = 1.0f / l_s[r0];
        const float inv1 = 1.0f / l_s[r1];
        float* y0 = y + ((size_t)b * TT + q0 + r0) * CC + h * DD;
        float* y1 = y + ((size_t)b * TT + q0 + r1) * CC + h * DD;
#pragma unroll
        for (int nt = 0; nt < 4; nt++) {
            const int c = (warp & 1) * 32 + nt * 8 + 2 * (lane & 3);
            float2 v0, v1;
            v0.x = __uint_as_float(f2tf32(oacc[nt][0] * inv0));
            v0.y = __uint_as_float(f2tf32(oacc[nt][1] * inv0));
            v1.x = __uint_as_float(f2tf32(oacc[nt][2] * inv1));
            v1.y = __uint_as_float(f2tf32(oacc[nt][3] * inv1));
            *(float2*)(y0 + c) = v0;
            *(float2*)(y1 + c) = v1;
        }
    }
}

// ---------------------------------------------------------------------------
extern "C" void kernel_launch(void* const* d_in, const int* in_sizes, int n_in,
                              void* d_out, int out_size)
{
    const float* x      = (const float*)d_in[0];
    const float* W_kqv  = (const float*)d_in[1];
    const float* b_kqv  = (const float*)d_in[2];
    const float* W_proj = (const float*)d_in[3];
    const float* b_proj = (const float*)d_in[4];
    const int*   pad    = (const int*)d_in[5];
    float* out = (float*)d_out;

    float *kqv_ptr, *y_ptr, *xr_ptr, *wk_ptr, *wp_ptr;
    cudaGetSymbolAddress((void**)&kqv_ptr, g_kqv);
    cudaGetSymbolAddress((void**)&y_ptr, g_y);
    cudaGetSymbolAddress((void**)&xr_ptr, g_xr);
    cudaGetSymbolAddress((void**)&wk_ptr, g_wk);
    cudaGetSymbolAddress((void**)&wp_ptr, g_wp);

    const int M = BB * TT;  // 8192

    cudaFuncSetAttribute(gemm_tf32_bias,
                         cudaFuncAttributeMaxDynamicSharedMemorySize, GSMEM);

    // 0) Prep: round x and weights to tf32 (natural layouts, no transpose)
    round_copy<<<(M * CC) / 1024, 256>>>(x, xr_ptr);
    round_copy<<<(CC * C3) / 1024, 256>>>(W_kqv, wk_ptr);
    round_copy<<<(CC * CC) / 1024, 256>>>(W_proj, wp_ptr);

    // 1) kqv = x @ W_kqv + b_kqv  [8192, 3072]
    {
        dim3 grid(C3 / 256, M / 128);
        gemm_tf32_bias<<<grid, 256, GSMEM>>>(xr_ptr, wk_ptr, b_kqv, kqv_ptr, C3);
    }
    // 2) flash attention -> y (tf32-rounded)  [8192, 1024]
    {
        dim3 grid(TT / BQ, HH, BB);
        attn_kernel<<<grid, 256>>>(kqv_ptr, pad, y_ptr);
    }
    // 3) out = y @ W_proj + b_proj  [8192, 1024]
    {
        dim3 grid(CC / 256, M / 128);
        gemm_tf32_bias<<<grid, 256, GSMEM>>>(y_ptr, wp_ptr, b_proj, out, CC);
    }
}

// round 9
// speedup vs baseline: 4.3244x; 1.3561x over previous
#include <cuda_runtime.h>
#include <cstdint>
#include <cstddef>

// Problem constants
#define BB 4
#define TT 2048
#define CC 1024
#define HH 16
#define DD 64
#define C3 (3 * CC)
#define GK 1024   // K of both dense GEMMs

// Scratch (allocation-free rule: __device__ globals)
__device__ float g_kqv[(size_t)BB * TT * C3];   // [B,T,3C]  (k | q | v)
__device__ float g_y[(size_t)BB * TT * CC];     // [B,T,C]   (tf32-rounded)
__device__ float g_xr[(size_t)BB * TT * CC];    // x rounded to tf32
__device__ float g_wk[(size_t)CC * C3];         // W_kqv rounded, natural [K,N]
__device__ float g_wp[(size_t)CC * CC];         // W_proj rounded, natural [K,N]

// ---------------------------------------------------------------------------
// Helpers
// ---------------------------------------------------------------------------
__device__ __forceinline__ uint32_t f2tf32(float x) {
    uint32_t r;
    asm("cvt.rna.tf32.f32 %0, %1;" : "=r"(r) : "f"(x));
    return r;
}

__device__ __forceinline__ void mma_tf32(float* d, const uint32_t* a, const uint32_t* b) {
    asm volatile(
        "mma.sync.aligned.m16n8k8.row.col.f32.tf32.tf32.f32 "
        "{%0,%1,%2,%3}, {%4,%5,%6,%7}, {%8,%9}, {%0,%1,%2,%3};"
        : "+f"(d[0]), "+f"(d[1]), "+f"(d[2]), "+f"(d[3])
        : "r"(a[0]), "r"(a[1]), "r"(a[2]), "r"(a[3]), "r"(b[0]), "r"(b[1]));
}

__device__ __forceinline__ uint32_t smem_u32(const void* p) {
    return (uint32_t)__cvta_generic_to_shared(p);
}
__device__ __forceinline__ void cp16(uint32_t s, const void* g) {
    asm volatile("cp.async.cg.shared.global [%0], [%1], 16;" :: "r"(s), "l"(g));
}
__device__ __forceinline__ void cp_commit() {
    asm volatile("cp.async.commit_group;" ::: "memory");
}
template <int n>
__device__ __forceinline__ void cp_wait() {
    asm volatile("cp.async.wait_group %0;" :: "n"(n) : "memory");
}
__device__ __forceinline__ uint32_t lds32(uint32_t a) {
    uint32_t v;
    asm volatile("ld.shared.b32 %0, [%1];" : "=r"(v) : "r"(a));
    return v;
}

#define SWZ128(o) ((o) ^ (((o) >> 3) & 0x70))

// ---------------------------------------------------------------------------
// Prep: tf32 rounding copy (1024 floats per block)
// ---------------------------------------------------------------------------
__global__ void round_copy(const float* __restrict__ in, float* __restrict__ out) {
    const int i = (blockIdx.x * 256 + threadIdx.x) * 4;
    float4 v = *(const float4*)(in + i);
    v.x = __uint_as_float(f2tf32(v.x));
    v.y = __uint_as_float(f2tf32(v.y));
    v.z = __uint_as_float(f2tf32(v.z));
    v.w = __uint_as_float(f2tf32(v.w));
    *(float4*)(out + i) = v;
}

// ---------------------------------------------------------------------------
// TF32 mma.sync GEMM with bias (unchanged from R8)
// ---------------------------------------------------------------------------
#define SMA(s) ((s) * 16384)
#define SMB(s) (32768 + (s) * 32768)
#define GSMEM  98304

__device__ __forceinline__ void gemm_copy_tile(
    uint32_t sb, int s, const float* __restrict__ A, const float* __restrict__ B,
    int bm, int bn, int k0, int N, int tid)
{
#pragma unroll
    for (int i = 0; i < 4; i++) {
        const int g = tid + i * 256;
        const int row = g >> 3;
        const int c16 = g & 7;
        const uint32_t so = sb + SMA(s) + SWZ128((uint32_t)(row * 128 + c16 * 16));
        cp16(so, A + (size_t)(bm + row) * GK + k0 + c16 * 4);
    }
#pragma unroll
    for (int i = 0; i < 8; i++) {
        const int g = tid + i * 256;
        const int k = g >> 6;
        const int c16 = g & 63;
        const uint32_t so = sb + SMB(s) + k * 1024 + ((c16 ^ ((k & 3) << 1)) << 4);
        cp16(so, B + (size_t)(k0 + k) * N + bn + c16 * 4);
    }
}

__global__ void __launch_bounds__(256, 1) gemm_tf32_bias(
    const float* __restrict__ A, const float* __restrict__ Bm,
    const float* __restrict__ bias, float* __restrict__ Cm, int N)
{
    extern __shared__ char smem[];
    const uint32_t sb = smem_u32(smem);
    const int tid  = threadIdx.x;
    const int warp = tid >> 5;
    const int lane = tid & 31;
    const int bm = blockIdx.y * 128;
    const int bn = blockIdx.x * 256;

    const int warpM = (warp >> 2) * 64;
    const int warpN = (warp & 3) * 64;

    float acc[4][8][4];
#pragma unroll
    for (int i = 0; i < 4; i++)
#pragma unroll
        for (int j = 0; j < 8; j++)
#pragma unroll
            for (int e = 0; e < 4; e++) acc[i][j][e] = 0.0f;

    gemm_copy_tile(sb, 0, A, Bm, bm, bn, 0, N, tid);
    cp_commit();
    gemm_copy_tile(sb, 1, A, Bm, bm, bn, 32, N, tid);
    cp_commit();

    const int lc = lane & 3;
    const int lr = lane >> 2;

    const int NT = GK / 32;
    for (int t = 0; t < NT; t++) {
        const int s = t & 1;
        cp_wait<1>();
        __syncthreads();

        const uint32_t aBase = sb + SMA(s);
        const uint32_t bBase = sb + SMB(s);
#pragma unroll
        for (int kc = 0; kc < 4; kc++) {
            uint32_t af[4][4];
#pragma unroll
            for (int mt = 0; mt < 4; mt++) {
                const int r0 = warpM + mt * 16 + lr;
                const int cb = (kc * 8 + lc) * 4;
                af[mt][0] = lds32(aBase + SWZ128((uint32_t)(r0 * 128 + cb)));
                af[mt][1] = lds32(aBase + SWZ128((uint32_t)((r0 + 8) * 128 + cb)));
                af[mt][2] = lds32(aBase + SWZ128((uint32_t)(r0 * 128 + cb + 16)));
                af[mt][3] = lds32(aBase + SWZ128((uint32_t)((r0 + 8) * 128 + cb + 16)));
            }
            uint32_t bf[8][2];
#pragma unroll
            for (int nt = 0; nt < 8; nt++) {
                const int n = warpN + nt * 8 + lr;
                const int k = kc * 8 + lc;
                const uint32_t swz = (uint32_t)(((n >> 2) ^ (lc << 1)) << 4) + ((n & 3) << 2);
                bf[nt][0] = lds32(bBase + k * 1024 + swz);
                bf[nt][1] = lds32(bBase + (k + 4) * 1024 + swz);
            }
#pragma unroll
            for (int mt = 0; mt < 4; mt++)
#pragma unroll
                for (int nt = 0; nt < 8; nt++)
                    mma_tf32(acc[mt][nt], af[mt], bf[nt]);
        }
        __syncthreads();

        if (t + 2 < NT) {
            gemm_copy_tile(sb, s, A, Bm, bm, bn, (t + 2) * 32, N, tid);
            cp_commit();
        }
    }

    const int r = lr, c2 = lc * 2;
#pragma unroll
    for (int mt = 0; mt < 4; mt++) {
#pragma unroll
        for (int nt = 0; nt < 8; nt++) {
            const int grow = bm + warpM + mt * 16 + r;
            const int gcol = bn + warpN + nt * 8 + c2;
            const float b0 = bias[gcol];
            const float b1 = bias[gcol + 1];
            float2 v0, v1;
            v0.x = acc[mt][nt][0] + b0;
            v0.y = acc[mt][nt][1] + b1;
            v1.x = acc[mt][nt][2] + b0;
            v1.y = acc[mt][nt][3] + b1;
            *(float2*)(Cm + (size_t)grow * N + gcol) = v0;
            *(float2*)(Cm + (size_t)(grow + 8) * N + gcol) = v1;
        }
    }
}

// ---------------------------------------------------------------------------
// Flash attention v3: BQ=128, BK=64, 8 warps x 16 rows, register softmax.
// K/V fragment smem: uint2-interleaved, per 8x8 block stride 66 u32 (padded).
//   off(nt,kc) block base = (nt*8+kc)*66; B-frag read = LDS.64 at +lane*2 (CF).
// Q staged once through smem into per-warp register A-fragments.
// Softmax entirely in registers (quad shuffles); P -> A-frags via quad shuffles.
// ---------------------------------------------------------------------------
#define AQ 128
#define AK 64
#define KVOFF 4224   // V frags base (u32); each tensor = 64 blocks * 66 = 4224 u32

__global__ void __launch_bounds__(256) attn_kernel(
    const float* __restrict__ kqv, const int* __restrict__ padmask,
    float* __restrict__ y)
{
    __shared__ uint32_t Sb[2 * KVOFF];   // 33 KB; also Q staging (8192 u32)
    __shared__ uint32_t padbits[2];

    const int q0 = blockIdx.x * AQ;
    const int h  = blockIdx.y;
    const int b  = blockIdx.z;
    const int tid = threadIdx.x;
    const int warp = tid >> 5;
    const int lane = tid & 31;
    const int q = lane & 3;
    const float c_scale = 0.18033688011112042f;  // 0.125 * log2(e)

    const float* base  = kqv + (size_t)b * TT * C3 + (size_t)h * DD;
    const float* qbase = base + CC;
    const float* kbase = base;
    const float* vbase = base + 2 * CC;

    // ---- Stage Q (128x64) into fragment-ordered smem, then to registers ----
    {
        const int r  = tid >> 1;          // 0..127
        const int kb = (tid & 1) * 32;    // 0 or 32
        const float* qp = qbase + (size_t)(q0 + r) * C3 + kb;
        const int mt = r >> 4;
        const int rr = r & 15;
        const int laneb = (rr & 7) * 4;
        const int ridx = rr >> 3;
#pragma unroll
        for (int j = 0; j < 8; j++) {
            float4 v = *(const float4*)(qp + 4 * j);
            const int k = kb + 4 * j;
            const int kc = k >> 3;
            const int reg = ridx + ((k >> 2) & 1) * 2;
            uint32_t* dst = &Sb[((mt * 8 + kc) * 32 + laneb) * 4 + reg];
            dst[0]  = f2tf32(v.x);
            dst[4]  = f2tf32(v.y);
            dst[8]  = f2tf32(v.z);
            dst[12] = f2tf32(v.w);
        }
    }
    __syncthreads();

    uint32_t aq_[8][4];
#pragma unroll
    for (int kc = 0; kc < 8; kc++)
        *(uint4*)aq_[kc] = *(const uint4*)&Sb[((warp * 8 + kc) * 32 + lane) * 4];

    const int r0 = warp * 16 + (lane >> 2);
    const int r1 = r0 + 8;

    float oacc[8][4];
#pragma unroll
    for (int nt = 0; nt < 8; nt++)
#pragma unroll
        for (int e = 0; e < 4; e++) oacc[nt][e] = 0.0f;
    float m0 = -1e20f, m1 = -1e20f, l0 = 0.0f, l1 = 0.0f;

    for (int j0 = 0; j0 < q0 + AQ; j0 += AK) {
        __syncthreads();   // prior tile compute done; Sb safe to overwrite

        // ---- Fill K/V fragment smem ----
        {
            const int jr = tid >> 2;          // key row 0..63
            const int db = (tid & 3) * 16;    // col base 0,16,32,48
            const size_t off = (size_t)(j0 + jr) * C3 + db;
            float kr[16], vr[16];
#pragma unroll
            for (int jj = 0; jj < 4; jj++) {
                float4 kv = *(const float4*)(kbase + off + 4 * jj);
                float4 vv = *(const float4*)(vbase + off + 4 * jj);
                kr[4 * jj + 0] = kv.x; kr[4 * jj + 1] = kv.y;
                kr[4 * jj + 2] = kv.z; kr[4 * jj + 3] = kv.w;
                vr[4 * jj + 0] = vv.x; vr[4 * jj + 1] = vv.y;
                vr[4 * jj + 2] = vv.z; vr[4 * jj + 3] = vv.w;
            }
            // K frags: nt=jr>>3, kc=col>>3, slot=(jr&7)*4+(col&3), reg=(col>>2)&1
            {
                const int nt = jr >> 3;
                const int slotb = (jr & 7) * 4;
#pragma unroll
                for (int g = 0; g < 2; g++) {
                    const int kc = (db >> 3) + g;
                    uint32_t* blk = &Sb[(nt * 8 + kc) * 66];
#pragma unroll
                    for (int e = 0; e < 4; e++) {
                        uint2 pr;
                        pr.x = f2tf32(kr[8 * g + e]);
                        pr.y = f2tf32(kr[8 * g + e + 4]);
                        *(uint2*)&blk[(slotb + e) * 2] = pr;
                    }
                }
            }
            // V frags: nt=col>>3, kc=jr>>3, slot=(col&7)*4+(jr&3), reg=(jr>>2)&1
            {
                const int kc = jr >> 3;
                const int regv = (jr >> 2) & 1;
                const int jr3 = jr & 3;
#pragma unroll
                for (int i = 0; i < 16; i++) {
                    const int c = db + i;
                    const int nt = c >> 3;
                    const int slot = (c & 7) * 4 + jr3;
                    Sb[KVOFF + (nt * 8 + kc) * 66 + slot * 2 + regv] = f2tf32(vr[i]);
                }
            }
        }
        if (warp == 0) {
            uint32_t p0 = __ballot_sync(0xffffffffu, padmask[b * TT + j0 + lane] != 0);
            uint32_t p1 = __ballot_sync(0xffffffffu, padmask[b * TT + j0 + 32 + lane] != 0);
            if (lane == 0) { padbits[0] = p0; padbits[1] = p1; }
        }
        __syncthreads();

        if (j0 > q0 + warp * 16 + 15) continue;   // warp-uniform skip

        // ---- S = Q K^T ----
        float sacc[8][4];
#pragma unroll
        for (int nt = 0; nt < 8; nt++)
#pragma unroll
            for (int e = 0; e < 4; e++) sacc[nt][e] = 0.0f;
#pragma unroll
        for (int kc = 0; kc < 8; kc++) {
#pragma unroll
            for (int nt = 0; nt < 8; nt++) {
                uint32_t bf[2];
                *(uint2*)bf = *(const uint2*)&Sb[(nt * 8 + kc) * 66 + lane * 2];
                mma_tf32(sacc[nt], aq_[kc], bf);
            }
        }

        // ---- Mask + scale (log2 domain) + row max ----
        const uint32_t pb0 = padbits[0], pb1 = padbits[1];
        const bool fast = (j0 + AK - 1 <= q0 + warp * 16) && (pb0 & pb1) == 0xffffffffu;
        float rm0 = -1e30f, rm1 = -1e30f;
        if (fast) {
#pragma unroll
            for (int nt = 0; nt < 8; nt++) {
#pragma unroll
                for (int e = 0; e < 4; e++) sacc[nt][e] *= c_scale;
                rm0 = fmaxf(rm0, fmaxf(sacc[nt][0], sacc[nt][1]));
                rm1 = fmaxf(rm1, fmaxf(sacc[nt][2], sacc[nt][3]));
            }
        } else {
#pragma unroll
            for (int nt = 0; nt < 8; nt++) {
                const int c0 = nt * 8 + 2 * q;
                const int c1 = c0 + 1;
                const bool p0v = (((c0 < 32 ? pb0 : pb1) >> (c0 & 31)) & 1u) != 0;
                const bool p1v = (((c1 < 32 ? pb0 : pb1) >> (c1 & 31)) & 1u) != 0;
                const int k0g = j0 + c0, k1g = j0 + c1;
                sacc[nt][0] = (p0v && k0g <= q0 + r0) ? sacc[nt][0] * c_scale : -1e30f;
                sacc[nt][1] = (p1v && k1g <= q0 + r0) ? sacc[nt][1] * c_scale : -1e30f;
                sacc[nt][2] = (p0v && k0g <= q0 + r1) ? sacc[nt][2] * c_scale : -1e30f;
                sacc[nt][3] = (p1v && k1g <= q0 + r1) ? sacc[nt][3] * c_scale : -1e30f;
                rm0 = fmaxf(rm0, fmaxf(sacc[nt][0], sacc[nt][1]));
                rm1 = fmaxf(rm1, fmaxf(sacc[nt][2], sacc[nt][3]));
            }
        }
        rm0 = fmaxf(rm0, __shfl_xor_sync(0xffffffffu, rm0, 1));
        rm0 = fmaxf(rm0, __shfl_xor_sync(0xffffffffu, rm0, 2));
        rm1 = fmaxf(rm1, __shfl_xor_sync(0xffffffffu, rm1, 1));
        rm1 = fmaxf(rm1, __shfl_xor_sync(0xffffffffu, rm1, 2));

        const float mn0 = fmaxf(m0, rm0);
        const float mn1 = fmaxf(m1, rm1);
        const float alpha0 = exp2f(m0 - mn0);
        const float alpha1 = exp2f(m1 - mn1);
        m0 = mn0; m1 = mn1;

        // ---- exp + row sums + rescale O ----
        float ps0 = 0.0f, ps1 = 0.0f;
#pragma unroll
        for (int nt = 0; nt < 8; nt++) {
            float p0 = exp2f(sacc[nt][0] - m0);
            float p1 = exp2f(sacc[nt][1] - m0);
            float p2 = exp2f(sacc[nt][2] - m1);
            float p3 = exp2f(sacc[nt][3] - m1);
            sacc[nt][0] = p0; sacc[nt][1] = p1;
            sacc[nt][2] = p2; sacc[nt][3] = p3;
            ps0 += p0 + p1; ps1 += p2 + p3;
            oacc[nt][0] *= alpha0; oacc[nt][1] *= alpha0;
            oacc[nt][2] *= alpha1; oacc[nt][3] *= alpha1;
        }
        ps0 += __shfl_xor_sync(0xffffffffu, ps0, 1);
        ps0 += __shfl_xor_sync(0xffffffffu, ps0, 2);
        ps1 += __shfl_xor_sync(0xffffffffu, ps1, 1);
        ps1 += __shfl_xor_sync(0xffffffffu, ps1, 2);
        l0 = l0 * alpha0 + ps0;
        l1 = l1 * alpha1 + ps1;

        // ---- O += P V : build P A-frags via quad shuffles ----
        const int sA = q >> 1;
        const bool odd = (q & 1) != 0;
#pragma unroll
        for (int kc = 0; kc < 8; kc++) {
            float t0 = __shfl_sync(0xffffffffu, sacc[kc][0], sA, 4);
            float t1 = __shfl_sync(0xffffffffu, sacc[kc][1], sA, 4);
            float t2 = __shfl_sync(0xffffffffu, sacc[kc][2], sA, 4);
            float t3 = __shfl_sync(0xffffffffu, sacc[kc][3], sA, 4);
            float u0 = __shfl_sync(0xffffffffu, sacc[kc][0], sA + 2, 4);
            float u1 = __shfl_sync(0xffffffffu, sacc[kc][1], sA + 2, 4);
            float u2 = __shfl_sync(0xffffffffu, sacc[kc][2], sA + 2, 4);
            float u3 = __shfl_sync(0xffffffffu, sacc[kc][3], sA + 2, 4);
            uint32_t a[4];
            a[0] = f2tf32(odd ? t1 : t0);   // (r0, q)
            a[1] = f2tf32(odd ? t3 : t2);   // (r1, q)
            a[2] = f2tf32(odd ? u1 : u0);   // (r0, q+4)
            a[3] = f2tf32(odd ? u3 : u2);   // (r1, q+4)
#pragma unroll
            for (int nt = 0; nt < 8; nt++) {
                uint32_t bv[2];
                *(uint2*)bv = *(const uint2*)&Sb[KVOFF + (nt * 8 + kc) * 66 + lane * 2];
                mma_tf32(oacc[nt], a, bv);
            }
        }
    }

    // ---- Epilogue: normalize + store y (tf32-rounded for proj GEMM) ----
    {
        const float inv0 = 1.0f / l0;
        const float inv1 = 1.0f / l1;
        float* y0 = y + ((size_t)b * TT + q0 + r0) * CC + h * DD;
        float* y1 = y + ((size_t)b * TT + q0 + r1) * CC + h * DD;
#pragma unroll
        for (int nt = 0; nt < 8; nt++) {
            const int c = nt * 8 + 2 * q;
            float2 v0, v1;
            v0.x = __uint_as_float(f2tf32(oacc[nt][0] * inv0));
            v0.y = __uint_as_float(f2tf32(oacc[nt][1] * inv0));
            v1.x = __uint_as_float(f2tf32(oacc[nt][2] * inv1));
            v1.y = __uint_as_float(f2tf32(oacc[nt][3] * inv1));
            *(float2*)(y0 + c) = v0;
            *(float2*)(y1 + c) = v1;
        }
    }
}

// ---------------------------------------------------------------------------
extern "C" void kernel_launch(void* const* d_in, const int* in_sizes, int n_in,
                              void* d_out, int out_size)
{
    const float* x      = (const float*)d_in[0];
    const float* W_kqv  = (const float*)d_in[1];
    const float* b_kqv  = (const float*)d_in[2];
    const float* W_proj = (const float*)d_in[3];
    const float* b_proj = (const float*)d_in[4];
    const int*   pad    = (const int*)d_in[5];
    float* out = (float*)d_out;

    float *kqv_ptr, *y_ptr, *xr_ptr, *wk_ptr, *wp_ptr;
    cudaGetSymbolAddress((void**)&kqv_ptr, g_kqv);
    cudaGetSymbolAddress((void**)&y_ptr, g_y);
    cudaGetSymbolAddress((void**)&xr_ptr, g_xr);
    cudaGetSymbolAddress((void**)&wk_ptr, g_wk);
    cudaGetSymbolAddress((void**)&wp_ptr, g_wp);

    const int M = BB * TT;  // 8192

    cudaFuncSetAttribute(gemm_tf32_bias,
                         cudaFuncAttributeMaxDynamicSharedMemorySize, GSMEM);

    // 0) Prep: round x and weights to tf32
    round_copy<<<(M * CC) / 1024, 256>>>(x, xr_ptr);
    round_copy<<<(CC * C3) / 1024, 256>>>(W_kqv, wk_ptr);
    round_copy<<<(CC * CC) / 1024, 256>>>(W_proj, wp_ptr);

    // 1) kqv = x @ W_kqv + b_kqv  [8192, 3072]
    {
        dim3 grid(C3 / 256, M / 128);
        gemm_tf32_bias<<<grid, 256, GSMEM>>>(xr_ptr, wk_ptr, b_kqv, kqv_ptr, C3);
    }
    // 2) flash attention -> y  [8192, 1024]
    {
        dim3 grid(TT / AQ, HH, BB);
        attn_kernel<<<grid, 256>>>(kqv_ptr, pad, y_ptr);
    }
    // 3) out = y @ W_proj + b_proj  [8192, 1024]
    {
        dim3 grid(CC / 256, M / 128);
        gemm_tf32_bias<<<grid, 256, GSMEM>>>(y_ptr, wp_ptr, b_proj, out, CC);
    }
}

// round 10
// speedup vs baseline: 4.4606x; 1.0315x over previous
#include <cuda_runtime.h>
#include <cstdint>
#include <cstddef>

// Problem constants
#define BB 4
#define TT 2048
#define CC 1024
#define HH 16
#define DD 64
#define C3 (3 * CC)
#define GK 1024   // K of both dense GEMMs

// Scratch (allocation-free rule: __device__ globals)
__device__ float g_kqv[(size_t)BB * TT * C3];   // [B,T,3C] (k|q|v), tf32-rounded
__device__ float g_y[(size_t)BB * TT * CC];     // [B,T,C]   (tf32-rounded)
__device__ float g_xr[(size_t)BB * TT * CC];    // x rounded to tf32
__device__ float g_wk[(size_t)CC * C3];         // W_kqv rounded, natural [K,N]
__device__ float g_wp[(size_t)CC * CC];         // W_proj rounded, natural [K,N]

// ---------------------------------------------------------------------------
// Helpers
// ---------------------------------------------------------------------------
__device__ __forceinline__ uint32_t f2tf32(float x) {
    uint32_t r;
    asm("cvt.rna.tf32.f32 %0, %1;" : "=r"(r) : "f"(x));
    return r;
}

__device__ __forceinline__ void mma_tf32(float* d, const uint32_t* a, const uint32_t* b) {
    asm volatile(
        "mma.sync.aligned.m16n8k8.row.col.f32.tf32.tf32.f32 "
        "{%0,%1,%2,%3}, {%4,%5,%6,%7}, {%8,%9}, {%0,%1,%2,%3};"
        : "+f"(d[0]), "+f"(d[1]), "+f"(d[2]), "+f"(d[3])
        : "r"(a[0]), "r"(a[1]), "r"(a[2]), "r"(a[3]), "r"(b[0]), "r"(b[1]));
}

__device__ __forceinline__ uint32_t smem_u32(const void* p) {
    return (uint32_t)__cvta_generic_to_shared(p);
}
__device__ __forceinline__ void cp16(uint32_t s, const void* g) {
    asm volatile("cp.async.cg.shared.global [%0], [%1], 16;" :: "r"(s), "l"(g));
}
__device__ __forceinline__ void cp_commit() {
    asm volatile("cp.async.commit_group;" ::: "memory");
}
template <int n>
__device__ __forceinline__ void cp_wait() {
    asm volatile("cp.async.wait_group %0;" :: "n"(n) : "memory");
}
__device__ __forceinline__ uint32_t lds32(uint32_t a) {
    uint32_t v;
    asm volatile("ld.shared.b32 %0, [%1];" : "=r"(v) : "r"(a));
    return v;
}

#define SWZ128(o) ((o) ^ (((o) >> 3) & 0x70))

// ---------------------------------------------------------------------------
// Prep: tf32 rounding copy (1024 floats per block)
// ---------------------------------------------------------------------------
__global__ void round_copy(const float* __restrict__ in, float* __restrict__ out) {
    const int i = (blockIdx.x * 256 + threadIdx.x) * 4;
    float4 v = *(const float4*)(in + i);
    v.x = __uint_as_float(f2tf32(v.x));
    v.y = __uint_as_float(f2tf32(v.y));
    v.z = __uint_as_float(f2tf32(v.z));
    v.w = __uint_as_float(f2tf32(v.w));
    *(float4*)(out + i) = v;
}

// ---------------------------------------------------------------------------
// TF32 mma.sync GEMM with bias (R8 kernel + round_out flag on the epilogue)
// ---------------------------------------------------------------------------
#define SMA(s) ((s) * 16384)
#define SMB(s) (32768 + (s) * 32768)
#define GSMEM  98304

__device__ __forceinline__ void gemm_copy_tile(
    uint32_t sb, int s, const float* __restrict__ A, const float* __restrict__ B,
    int bm, int bn, int k0, int N, int tid)
{
#pragma unroll
    for (int i = 0; i < 4; i++) {
        const int g = tid + i * 256;
        const int row = g >> 3;
        const int c16 = g & 7;
        const uint32_t so = sb + SMA(s) + SWZ128((uint32_t)(row * 128 + c16 * 16));
        cp16(so, A + (size_t)(bm + row) * GK + k0 + c16 * 4);
    }
#pragma unroll
    for (int i = 0; i < 8; i++) {
        const int g = tid + i * 256;
        const int k = g >> 6;
        const int c16 = g & 63;
        const uint32_t so = sb + SMB(s) + k * 1024 + ((c16 ^ ((k & 3) << 1)) << 4);
        cp16(so, B + (size_t)(k0 + k) * N + bn + c16 * 4);
    }
}

__global__ void __launch_bounds__(256, 1) gemm_tf32_bias(
    const float* __restrict__ A, const float* __restrict__ Bm,
    const float* __restrict__ bias, float* __restrict__ Cm, int N, int round_out)
{
    extern __shared__ char smem[];
    const uint32_t sb = smem_u32(smem);
    const int tid  = threadIdx.x;
    const int warp = tid >> 5;
    const int lane = tid & 31;
    const int bm = blockIdx.y * 128;
    const int bn = blockIdx.x * 256;

    const int warpM = (warp >> 2) * 64;
    const int warpN = (warp & 3) * 64;

    float acc[4][8][4];
#pragma unroll
    for (int i = 0; i < 4; i++)
#pragma unroll
        for (int j = 0; j < 8; j++)
#pragma unroll
            for (int e = 0; e < 4; e++) acc[i][j][e] = 0.0f;

    gemm_copy_tile(sb, 0, A, Bm, bm, bn, 0, N, tid);
    cp_commit();
    gemm_copy_tile(sb, 1, A, Bm, bm, bn, 32, N, tid);
    cp_commit();

    const int lc = lane & 3;
    const int lr = lane >> 2;

    const int NT = GK / 32;
    for (int t = 0; t < NT; t++) {
        const int s = t & 1;
        cp_wait<1>();
        __syncthreads();

        const uint32_t aBase = sb + SMA(s);
        const uint32_t bBase = sb + SMB(s);
#pragma unroll
        for (int kc = 0; kc < 4; kc++) {
            uint32_t af[4][4];
#pragma unroll
            for (int mt = 0; mt < 4; mt++) {
                const int r0 = warpM + mt * 16 + lr;
                const int cb = (kc * 8 + lc) * 4;
                af[mt][0] = lds32(aBase + SWZ128((uint32_t)(r0 * 128 + cb)));
                af[mt][1] = lds32(aBase + SWZ128((uint32_t)((r0 + 8) * 128 + cb)));
                af[mt][2] = lds32(aBase + SWZ128((uint32_t)(r0 * 128 + cb + 16)));
                af[mt][3] = lds32(aBase + SWZ128((uint32_t)((r0 + 8) * 128 + cb + 16)));
            }
            uint32_t bf[8][2];
#pragma unroll
            for (int nt = 0; nt < 8; nt++) {
                const int n = warpN + nt * 8 + lr;
                const int k = kc * 8 + lc;
                const uint32_t swz = (uint32_t)(((n >> 2) ^ (lc << 1)) << 4) + ((n & 3) << 2);
                bf[nt][0] = lds32(bBase + k * 1024 + swz);
                bf[nt][1] = lds32(bBase + (k + 4) * 1024 + swz);
            }
#pragma unroll
            for (int mt = 0; mt < 4; mt++)
#pragma unroll
                for (int nt = 0; nt < 8; nt++)
                    mma_tf32(acc[mt][nt], af[mt], bf[nt]);
        }
        __syncthreads();

        if (t + 2 < NT) {
            gemm_copy_tile(sb, s, A, Bm, bm, bn, (t + 2) * 32, N, tid);
            cp_commit();
        }
    }

    const int r = lr, c2 = lc * 2;
#pragma unroll
    for (int mt = 0; mt < 4; mt++) {
#pragma unroll
        for (int nt = 0; nt < 8; nt++) {
            const int grow = bm + warpM + mt * 16 + r;
            const int gcol = bn + warpN + nt * 8 + c2;
            const float b0 = bias[gcol];
            const float b1 = bias[gcol + 1];
            float2 v0, v1;
            v0.x = acc[mt][nt][0] + b0;
            v0.y = acc[mt][nt][1] + b1;
            v1.x = acc[mt][nt][2] + b0;
            v1.y = acc[mt][nt][3] + b1;
            if (round_out) {
                v0.x = __uint_as_float(f2tf32(v0.x));
                v0.y = __uint_as_float(f2tf32(v0.y));
                v1.x = __uint_as_float(f2tf32(v1.x));
                v1.y = __uint_as_float(f2tf32(v1.y));
            }
            *(float2*)(Cm + (size_t)grow * N + gcol) = v0;
            *(float2*)(Cm + (size_t)(grow + 8) * N + gcol) = v1;
        }
    }
}

// ---------------------------------------------------------------------------
// Flash attention v4: BQ=128, BK=64, register softmax (R9) + cp.async
// double-buffered K/V in fragment-plane layouts (kqv pre-rounded to tf32).
//
// K block (nt=key/8, kc=d/8), 256B: [reg=(d>>2)&1][j&7][d&3] u32
//   write (j,d):  bi*256 + reg*128 + (j&7)*16 + (d&3)*4   (16B chunks contig)
//   read lane:    bi*256 + lane*4  (+128)                  conflict-free
// V block (nt=d/8, kc=key/8), 256B: [reg=(j>>2)&1][j&3][d&7] u32
//   write (j,d):  bi*256 + reg*128 + (j&3)*32 + (d&7)*4
//   read lane:    bi*256 + (lane&3)*32 + (lane>>2)*4 (+128) conflict-free
// Stage s (32KB): K @ s*32768, V @ s*32768 + 16384.  Q staged in stage 0+.
// ---------------------------------------------------------------------------
#define AQ 128
#define AK 64
#define ASMEM 65536

__device__ __forceinline__ void attn_fill(
    uint32_t sb, int s, const float* __restrict__ kb, const float* __restrict__ vb,
    int j0, int tid)
{
    const uint32_t sK = sb + s * 32768;
    const uint32_t sV = sK + 16384;
#pragma unroll
    for (int i = 0; i < 4; i++) {
        const int c = tid + i * 256;          // 0..1023 16B chunks
        const int j = c >> 4;                 // key row 0..63
        const int d = (c & 15) << 2;          // col 0..60 step 4
        const size_t goff = (size_t)(j0 + j) * C3 + d;
        const uint32_t kdst = sK + (((j >> 3) * 8 + (d >> 3)) << 8)
                            + (((d >> 2) & 1) << 7) + ((j & 7) << 4);
        cp16(kdst, kb + goff);
        const uint32_t vdst = sV + (((d >> 3) * 8 + (j >> 3)) << 8)
                            + (((j >> 2) & 1) << 7) + ((j & 3) << 5) + ((d & 4) << 2);
        cp16(vdst, vb + goff);
    }
}

__global__ void __launch_bounds__(256) attn_kernel(
    const float* __restrict__ kqv, const int* __restrict__ padmask,
    float* __restrict__ y)
{
    extern __shared__ char asmem[];
    const uint32_t sb = smem_u32(asmem);
    uint32_t* const Sb = (uint32_t*)asmem;

    const int q0 = blockIdx.x * AQ;
    const int h  = blockIdx.y;
    const int b  = blockIdx.z;
    const int tid = threadIdx.x;
    const int warp = tid >> 5;
    const int lane = tid & 31;
    const int q = lane & 3;
    const float c_scale = 0.18033688011112042f;  // 0.125 * log2(e)

    const float* base  = kqv + (size_t)b * TT * C3 + (size_t)h * DD;
    const float* qbase = base + CC;
    const float* kbase = base;
    const float* vbase = base + 2 * CC;

    // ---- Stage Q (128x64) into fragment-ordered smem, then to registers ----
    {
        const int r  = tid >> 1;          // 0..127
        const int kb = (tid & 1) * 32;    // 0 or 32
        const float* qp = qbase + (size_t)(q0 + r) * C3 + kb;
        const int mt = r >> 4;
        const int rr = r & 15;
        const int laneb = (rr & 7) * 4;
        const int ridx = rr >> 3;
#pragma unroll
        for (int j = 0; j < 8; j++) {
            float4 v = *(const float4*)(qp + 4 * j);
            const int k = kb + 4 * j;
            const int kc = k >> 3;
            const int reg = ridx + ((k >> 2) & 1) * 2;
            uint32_t* dst = &Sb[((mt * 8 + kc) * 32 + laneb) * 4 + reg];
            dst[0]  = __float_as_uint(v.x);   // kqv already tf32-rounded
            dst[4]  = __float_as_uint(v.y);
            dst[8]  = __float_as_uint(v.z);
            dst[12] = __float_as_uint(v.w);
        }
    }
    __syncthreads();

    uint32_t aq_[8][4];
#pragma unroll
    for (int kc = 0; kc < 8; kc++)
        *(uint4*)aq_[kc] = *(const uint4*)&Sb[((warp * 8 + kc) * 32 + lane) * 4];
    __syncthreads();   // Q regs loaded; smem free for K/V stages

    const int r0 = warp * 16 + (lane >> 2);
    const int r1 = r0 + 8;

    float oacc[8][4];
#pragma unroll
    for (int nt = 0; nt < 8; nt++)
#pragma unroll
        for (int e = 0; e < 4; e++) oacc[nt][e] = 0.0f;
    float m0 = -1e20f, m1 = -1e20f, l0 = 0.0f, l1 = 0.0f;

    const int ntiles = (q0 + AQ) / AK;   // >= 2

    // Prologue: fill tiles 0 and 1
    attn_fill(sb, 0, kbase, vbase, 0, tid);
    cp_commit();
    attn_fill(sb, 1, kbase, vbase, AK, tid);
    cp_commit();

    for (int t = 0; t < ntiles; t++) {
        const int s = t & 1;
        const int j0 = t * AK;
        cp_wait<1>();
        __syncthreads();

        const bool active = (j0 <= q0 + warp * 16 + 15);  // warp-uniform
        if (active) {
            const uint32_t sK = sb + s * 32768;
            const uint32_t sV = sK + 16384;

            // padmask bits for this tile (per-warp, no smem)
            const uint32_t pb0 =
                __ballot_sync(0xffffffffu, padmask[b * TT + j0 + lane] != 0);
            const uint32_t pb1 =
                __ballot_sync(0xffffffffu, padmask[b * TT + j0 + 32 + lane] != 0);

            // ---- S = Q K^T ----
            float sacc[8][4];
#pragma unroll
            for (int nt = 0; nt < 8; nt++)
#pragma unroll
                for (int e = 0; e < 4; e++) sacc[nt][e] = 0.0f;
#pragma unroll
            for (int kc = 0; kc < 8; kc++) {
#pragma unroll
                for (int nt = 0; nt < 8; nt++) {
                    const uint32_t a = sK + ((nt * 8 + kc) << 8) + lane * 4;
                    uint32_t bf[2];
                    bf[0] = lds32(a);
                    bf[1] = lds32(a + 128);
                    mma_tf32(sacc[nt], aq_[kc], bf);
                }
            }

            // ---- Mask + scale (log2 domain) + row max ----
            const bool fast =
                (j0 + AK - 1 <= q0 + warp * 16) && (pb0 & pb1) == 0xffffffffu;
            float rm0 = -1e30f, rm1 = -1e30f;
            if (fast) {
#pragma unroll
                for (int nt = 0; nt < 8; nt++) {
#pragma unroll
                    for (int e = 0; e < 4; e++) sacc[nt][e] *= c_scale;
                    rm0 = fmaxf(rm0, fmaxf(sacc[nt][0], sacc[nt][1]));
                    rm1 = fmaxf(rm1, fmaxf(sacc[nt][2], sacc[nt][3]));
                }
            } else {
#pragma unroll
                for (int nt = 0; nt < 8; nt++) {
                    const int c0 = nt * 8 + 2 * q;
                    const int c1 = c0 + 1;
                    const bool p0v = (((c0 < 32 ? pb0 : pb1) >> (c0 & 31)) & 1u) != 0;
                    const bool p1v = (((c1 < 32 ? pb0 : pb1) >> (c1 & 31)) & 1u) != 0;
                    const int k0g = j0 + c0, k1g = j0 + c1;
                    sacc[nt][0] = (p0v && k0g <= q0 + r0) ? sacc[nt][0] * c_scale : -1e30f;
                    sacc[nt][1] = (p1v && k1g <= q0 + r0) ? sacc[nt][1] * c_scale : -1e30f;
                    sacc[nt][2] = (p0v && k0g <= q0 + r1) ? sacc[nt][2] * c_scale : -1e30f;
                    sacc[nt][3] = (p1v && k1g <= q0 + r1) ? sacc[nt][3] * c_scale : -1e30f;
                    rm0 = fmaxf(rm0, fmaxf(sacc[nt][0], sacc[nt][1]));
                    rm1 = fmaxf(rm1, fmaxf(sacc[nt][2], sacc[nt][3]));
                }
            }
            rm0 = fmaxf(rm0, __shfl_xor_sync(0xffffffffu, rm0, 1));
            rm0 = fmaxf(rm0, __shfl_xor_sync(0xffffffffu, rm0, 2));
            rm1 = fmaxf(rm1, __shfl_xor_sync(0xffffffffu, rm1, 1));
            rm1 = fmaxf(rm1, __shfl_xor_sync(0xffffffffu, rm1, 2));

            const float mn0 = fmaxf(m0, rm0);
            const float mn1 = fmaxf(m1, rm1);
            const float alpha0 = exp2f(m0 - mn0);
            const float alpha1 = exp2f(m1 - mn1);
            m0 = mn0; m1 = mn1;

            float ps0 = 0.0f, ps1 = 0.0f;
#pragma unroll
            for (int nt = 0; nt < 8; nt++) {
                float p0 = exp2f(sacc[nt][0] - m0);
                float p1 = exp2f(sacc[nt][1] - m0);
                float p2 = exp2f(sacc[nt][2] - m1);
                float p3 = exp2f(sacc[nt][3] - m1);
                sacc[nt][0] = p0; sacc[nt][1] = p1;
                sacc[nt][2] = p2; sacc[nt][3] = p3;
                ps0 += p0 + p1; ps1 += p2 + p3;
                oacc[nt][0] *= alpha0; oacc[nt][1] *= alpha0;
                oacc[nt][2] *= alpha1; oacc[nt][3] *= alpha1;
            }
            ps0 += __shfl_xor_sync(0xffffffffu, ps0, 1);
            ps0 += __shfl_xor_sync(0xffffffffu, ps0, 2);
            ps1 += __shfl_xor_sync(0xffffffffu, ps1, 1);
            ps1 += __shfl_xor_sync(0xffffffffu, ps1, 2);
            l0 = l0 * alpha0 + ps0;
            l1 = l1 * alpha1 + ps1;

            // ---- O += P V : P A-frags via quad shuffles ----
            const int sA = q >> 1;
            const bool odd = (q & 1) != 0;
#pragma unroll
            for (int kc = 0; kc < 8; kc++) {
                float t0 = __shfl_sync(0xffffffffu, sacc[kc][0], sA, 4);
                float t1 = __shfl_sync(0xffffffffu, sacc[kc][1], sA, 4);
                float t2 = __shfl_sync(0xffffffffu, sacc[kc][2], sA, 4);
                float t3 = __shfl_sync(0xffffffffu, sacc[kc][3], sA, 4);
                float u0 = __shfl_sync(0xffffffffu, sacc[kc][0], sA + 2, 4);
                float u1 = __shfl_sync(0xffffffffu, sacc[kc][1], sA + 2, 4);
                float u2 = __shfl_sync(0xffffffffu, sacc[kc][2], sA + 2, 4);
                float u3 = __shfl_sync(0xffffffffu, sacc[kc][3], sA + 2, 4);
                uint32_t a[4];
                a[0] = f2tf32(odd ? t1 : t0);
                a[1] = f2tf32(odd ? t3 : t2);
                a[2] = f2tf32(odd ? u1 : u0);
                a[3] = f2tf32(odd ? u3 : u2);
#pragma unroll
                for (int nt = 0; nt < 8; nt++) {
                    const uint32_t ad = sV + ((nt * 8 + kc) << 8)
                                      + ((lane & 3) << 5) + ((lane >> 2) << 2);
                    uint32_t bv[2];
                    bv[0] = lds32(ad);
                    bv[1] = lds32(ad + 128);
                    mma_tf32(oacc[nt], a, bv);
                }
            }
        }
        __syncthreads();   // all warps done with stage s before refill

        if (t + 2 < ntiles)
            attn_fill(sb, s, kbase, vbase, (t + 2) * AK, tid);
        cp_commit();
    }

    // ---- Epilogue: normalize + store y (tf32-rounded for proj GEMM) ----
    {
        const float inv0 = 1.0f / l0;
        const float inv1 = 1.0f / l1;
        float* y0 = y + ((size_t)b * TT + q0 + r0) * CC + h * DD;
        float* y1 = y + ((size_t)b * TT + q0 + r1) * CC + h * DD;
#pragma unroll
        for (int nt = 0; nt < 8; nt++) {
            const int c = nt * 8 + 2 * q;
            float2 v0, v1;
            v0.x = __uint_as_float(f2tf32(oacc[nt][0] * inv0));
            v0.y = __uint_as_float(f2tf32(oacc[nt][1] * inv0));
            v1.x = __uint_as_float(f2tf32(oacc[nt][2] * inv1));
            v1.y = __uint_as_float(f2tf32(oacc[nt][3] * inv1));
            *(float2*)(y0 + c) = v0;
            *(float2*)(y1 + c) = v1;
        }
    }
}

// ---------------------------------------------------------------------------
extern "C" void kernel_launch(void* const* d_in, const int* in_sizes, int n_in,
                              void* d_out, int out_size)
{
    const float* x      = (const float*)d_in[0];
    const float* W_kqv  = (const float*)d_in[1];
    const float* b_kqv  = (const float*)d_in[2];
    const float* W_proj = (const float*)d_in[3];
    const float* b_proj = (const float*)d_in[4];
    const int*   pad    = (const int*)d_in[5];
    float* out = (float*)d_out;

    float *kqv_ptr, *y_ptr, *xr_ptr, *wk_ptr, *wp_ptr;
    cudaGetSymbolAddress((void**)&kqv_ptr, g_kqv);
    cudaGetSymbolAddress((void**)&y_ptr, g_y);
    cudaGetSymbolAddress((void**)&xr_ptr, g_xr);
    cudaGetSymbolAddress((void**)&wk_ptr, g_wk);
    cudaGetSymbolAddress((void**)&wp_ptr, g_wp);

    const int M = BB * TT;  // 8192

    cudaFuncSetAttribute(gemm_tf32_bias,
                         cudaFuncAttributeMaxDynamicSharedMemorySize, GSMEM);
    cudaFuncSetAttribute(attn_kernel,
                         cudaFuncAttributeMaxDynamicSharedMemorySize, ASMEM);

    // 0) Prep: round x and weights to tf32
    round_copy<<<(M * CC) / 1024, 256>>>(x, xr_ptr);
    round_copy<<<(CC * C3) / 1024, 256>>>(W_kqv, wk_ptr);
    round_copy<<<(CC * CC) / 1024, 256>>>(W_proj, wp_ptr);

    // 1) kqv = x @ W_kqv + b_kqv  [8192, 3072], output tf32-rounded
    {
        dim3 grid(C3 / 256, M / 128);
        gemm_tf32_bias<<<grid, 256, GSMEM>>>(xr_ptr, wk_ptr, b_kqv, kqv_ptr, C3, 1);
    }
    // 2) flash attention -> y  [8192, 1024]
    {
        dim3 grid(TT / AQ, HH, BB);
        attn_kernel<<<grid, 256, ASMEM>>>(kqv_ptr, pad, y_ptr);
    }
    // 3) out = y @ W_proj + b_proj  [8192, 1024], fp32 output
    {
        dim3 grid(CC / 256, M / 128);
        gemm_tf32_bias<<<grid, 256, GSMEM>>>(y_ptr, wp_ptr, b_proj, out, CC, 0);
    }
}

// round 12
// speedup vs baseline: 5.9268x; 1.3287x over previous
#include <cuda_runtime.h>
#include <cuda_fp16.h>
#include <cstdint>
#include <cstddef>

// Problem constants
#define BB 4
#define TT 2048
#define CC 1024
#define HH 16
#define DD 64
#define C3 (3 * CC)
#define GK 1024   // K of both dense GEMMs

// Scratch (allocation-free rule: __device__ globals)
__device__ __half g_kqvh[(size_t)BB * TT * C3]; // [B,T,3C] (k|q|v) fp16
__device__ float  g_y[(size_t)BB * TT * CC];    // [B,T,C] tf32-rounded
__device__ float  g_xr[(size_t)BB * TT * CC];   // x rounded to tf32
__device__ float  g_wk[(size_t)CC * C3];        // W_kqv rounded, natural [K,N]
__device__ float  g_wp[(size_t)CC * CC];        // W_proj rounded, natural [K,N]

// ---------------------------------------------------------------------------
// Helpers
// ---------------------------------------------------------------------------
__device__ __forceinline__ uint32_t f2tf32(float x) {
    uint32_t r;
    asm("cvt.rna.tf32.f32 %0, %1;" : "=r"(r) : "f"(x));
    return r;
}
__device__ __forceinline__ uint32_t packh2(float lo, float hi) {
    uint32_t r;
    asm("cvt.rn.f16x2.f32 %0, %1, %2;" : "=r"(r) : "f"(hi), "f"(lo));
    return r;
}

__device__ __forceinline__ void mma_tf32(float* d, const uint32_t* a, const uint32_t* b) {
    asm volatile(
        "mma.sync.aligned.m16n8k8.row.col.f32.tf32.tf32.f32 "
        "{%0,%1,%2,%3}, {%4,%5,%6,%7}, {%8,%9}, {%0,%1,%2,%3};"
        : "+f"(d[0]), "+f"(d[1]), "+f"(d[2]), "+f"(d[3])
        : "r"(a[0]), "r"(a[1]), "r"(a[2]), "r"(a[3]), "r"(b[0]), "r"(b[1]));
}
__device__ __forceinline__ void mma_f16(float* d, const uint32_t* a, const uint32_t* b) {
    asm volatile(
        "mma.sync.aligned.m16n8k16.row.col.f32.f16.f16.f32 "
        "{%0,%1,%2,%3}, {%4,%5,%6,%7}, {%8,%9}, {%0,%1,%2,%3};"
        : "+f"(d[0]), "+f"(d[1]), "+f"(d[2]), "+f"(d[3])
        : "r"(a[0]), "r"(a[1]), "r"(a[2]), "r"(a[3]), "r"(b[0]), "r"(b[1]));
}
__device__ __forceinline__ void ldsm4(uint32_t* r, uint32_t addr) {
    asm volatile("ldmatrix.sync.aligned.m8n8.x4.shared.b16 {%0,%1,%2,%3}, [%4];"
                 : "=r"(r[0]), "=r"(r[1]), "=r"(r[2]), "=r"(r[3]) : "r"(addr));
}
__device__ __forceinline__ void ldsm4t(uint32_t* r, uint32_t addr) {
    asm volatile("ldmatrix.sync.aligned.m8n8.x4.trans.shared.b16 {%0,%1,%2,%3}, [%4];"
                 : "=r"(r[0]), "=r"(r[1]), "=r"(r[2]), "=r"(r[3]) : "r"(addr));
}

__device__ __forceinline__ uint32_t smem_u32(const void* p) {
    return (uint32_t)__cvta_generic_to_shared(p);
}
__device__ __forceinline__ void cp16(uint32_t s, const void* g) {
    asm volatile("cp.async.cg.shared.global [%0], [%1], 16;" :: "r"(s), "l"(g));
}
__device__ __forceinline__ void cp_commit() {
    asm volatile("cp.async.commit_group;" ::: "memory");
}
template <int n>
__device__ __forceinline__ void cp_wait() {
    asm volatile("cp.async.wait_group %0;" :: "n"(n) : "memory");
}
__device__ __forceinline__ uint32_t lds32(uint32_t a) {
    uint32_t v;
    asm volatile("ld.shared.b32 %0, [%1];" : "=r"(v) : "r"(a));
    return v;
}

#define SWZ128(o) ((o) ^ (((o) >> 3) & 0x70))

// ---------------------------------------------------------------------------
// Prep: tf32 rounding copy (1024 floats per block)
// ---------------------------------------------------------------------------
__global__ void round_copy(const float* __restrict__ in, float* __restrict__ out) {
    const int i = (blockIdx.x * 256 + threadIdx.x) * 4;
    float4 v = *(const float4*)(in + i);
    v.x = __uint_as_float(f2tf32(v.x));
    v.y = __uint_as_float(f2tf32(v.y));
    v.z = __uint_as_float(f2tf32(v.z));
    v.w = __uint_as_float(f2tf32(v.w));
    *(float4*)(out + i) = v;
}

// ---------------------------------------------------------------------------
// TF32 mma.sync GEMM with bias; epilogue writes fp32 or fp16 (half_out).
// ---------------------------------------------------------------------------
#define SMA(s) ((s) * 16384)
#define SMB(s) (32768 + (s) * 32768)
#define GSMEM  98304

__device__ __forceinline__ void gemm_copy_tile(
    uint32_t sb, int s, const float* __restrict__ A, const float* __restrict__ B,
    int bm, int bn, int k0, int N, int tid)
{
#pragma unroll
    for (int i = 0; i < 4; i++) {
        const int g = tid + i * 256;
        const int row = g >> 3;
        const int c16 = g & 7;
        const uint32_t so = sb + SMA(s) + SWZ128((uint32_t)(row * 128 + c16 * 16));
        cp16(so, A + (size_t)(bm + row) * GK + k0 + c16 * 4);
    }
#pragma unroll
    for (int i = 0; i < 8; i++) {
        const int g = tid + i * 256;
        const int k = g >> 6;
        const int c16 = g & 63;
        const uint32_t so = sb + SMB(s) + k * 1024 + ((c16 ^ ((k & 3) << 1)) << 4);
        cp16(so, B + (size_t)(k0 + k) * N + bn + c16 * 4);
    }
}

__global__ void __launch_bounds__(256, 1) gemm_tf32_bias(
    const float* __restrict__ A, const float* __restrict__ Bm,
    const float* __restrict__ bias, void* __restrict__ Cm, int N, int half_out)
{
    extern __shared__ char smem[];
    const uint32_t sb = smem_u32(smem);
    const int tid  = threadIdx.x;
    const int warp = tid >> 5;
    const int lane = tid & 31;
    const int bm = blockIdx.y * 128;
    const int bn = blockIdx.x * 256;

    const int warpM = (warp >> 2) * 64;
    const int warpN = (warp & 3) * 64;

    float acc[4][8][4];
#pragma unroll
    for (int i = 0; i < 4; i++)
#pragma unroll
        for (int j = 0; j < 8; j++)
#pragma unroll
            for (int e = 0; e < 4; e++) acc[i][j][e] = 0.0f;

    gemm_copy_tile(sb, 0, A, Bm, bm, bn, 0, N, tid);
    cp_commit();
    gemm_copy_tile(sb, 1, A, Bm, bm, bn, 32, N, tid);
    cp_commit();

    const int lc = lane & 3;
    const int lr = lane >> 2;

    const int NT = GK / 32;
    for (int t = 0; t < NT; t++) {
        const int s = t & 1;
        cp_wait<1>();
        __syncthreads();

        const uint32_t aBase = sb + SMA(s);
        const uint32_t bBase = sb + SMB(s);
#pragma unroll
        for (int kc = 0; kc < 4; kc++) {
            uint32_t af[4][4];
#pragma unroll
            for (int mt = 0; mt < 4; mt++) {
                const int r0 = warpM + mt * 16 + lr;
                const int cb = (kc * 8 + lc) * 4;
                af[mt][0] = lds32(aBase + SWZ128((uint32_t)(r0 * 128 + cb)));
                af[mt][1] = lds32(aBase + SWZ128((uint32_t)((r0 + 8) * 128 + cb)));
                af[mt][2] = lds32(aBase + SWZ128((uint32_t)(r0 * 128 + cb + 16)));
                af[mt][3] = lds32(aBase + SWZ128((uint32_t)((r0 + 8) * 128 + cb + 16)));
            }
            uint32_t bf[8][2];
#pragma unroll
            for (int nt = 0; nt < 8; nt++) {
                const int n = warpN + nt * 8 + lr;
                const int k = kc * 8 + lc;
                const uint32_t swz = (uint32_t)(((n >> 2) ^ (lc << 1)) << 4) + ((n & 3) << 2);
                bf[nt][0] = lds32(bBase + k * 1024 + swz);
                bf[nt][1] = lds32(bBase + (k + 4) * 1024 + swz);
            }
#pragma unroll
            for (int mt = 0; mt < 4; mt++)
#pragma unroll
                for (int nt = 0; nt < 8; nt++)
                    mma_tf32(acc[mt][nt], af[mt], bf[nt]);
        }
        __syncthreads();

        if (t + 2 < NT) {
            gemm_copy_tile(sb, s, A, Bm, bm, bn, (t + 2) * 32, N, tid);
            cp_commit();
        }
    }

    const int r = lr, c2 = lc * 2;
#pragma unroll
    for (int mt = 0; mt < 4; mt++) {
#pragma unroll
        for (int nt = 0; nt < 8; nt++) {
            const int grow = bm + warpM + mt * 16 + r;
            const int gcol = bn + warpN + nt * 8 + c2;
            const float b0 = bias[gcol];
            const float b1 = bias[gcol + 1];
            const float v00 = acc[mt][nt][0] + b0;
            const float v01 = acc[mt][nt][1] + b1;
            const float v10 = acc[mt][nt][2] + b0;
            const float v11 = acc[mt][nt][3] + b1;
            if (half_out) {
                uint32_t* co = (uint32_t*)Cm;
                co[((size_t)grow * N + gcol) >> 1]       = packh2(v00, v01);
                co[((size_t)(grow + 8) * N + gcol) >> 1] = packh2(v10, v11);
            } else {
                float* cf = (float*)Cm;
                *(float2*)(cf + (size_t)grow * N + gcol)       = make_float2(v00, v01);
                *(float2*)(cf + (size_t)(grow + 8) * N + gcol) = make_float2(v10, v11);
            }
        }
    }
}

// ---------------------------------------------------------------------------
// Flash attention v5: fp16 m16n8k16 + ldmatrix, BQ=128, BK=64, reg softmax.
// smem: Q 128x64 fp16 @0 (16KB, SW128 rows of 128B); K/V stages:
//   stage s @ 16384 + s*16384; K @ +0 (8KB), V @ +8192 (8KB); both row-major
//   [row][64 halves] with SW128 swizzle. Total 48KB dynamic.
// Q A-frags / K B-frags via ldmatrix.x4; V B-frags via ldmatrix.x4.trans.
// P C-frag pairs == A-frag pairs -> pack with cvt.rn.f16x2 (no shuffles).
// ---------------------------------------------------------------------------
#define AQ 128
#define AK 64
#define ASMEM 49152

__device__ __forceinline__ void attn_fill(
    uint32_t sK, uint32_t sV, const __half* __restrict__ kb,
    const __half* __restrict__ vb, int j0, int tid)
{
#pragma unroll
    for (int i = 0; i < 4; i++) {
        const int cc = tid + (i & 1) * 256;   // 0..511
        const int j = cc >> 3;
        const int c8 = cc & 7;
        const uint32_t off = SWZ128((uint32_t)(j * 128 + c8 * 16));
        if (i < 2) cp16(sK + off, kb + (size_t)(j0 + j) * C3 + c8 * 8);
        else       cp16(sV + off, vb + (size_t)(j0 + j) * C3 + c8 * 8);
    }
}

__global__ void __launch_bounds__(256) attn_kernel(
    const __half* __restrict__ kqvh, const int* __restrict__ padmask,
    float* __restrict__ y)
{
    extern __shared__ char asmem[];
    const uint32_t sb = smem_u32(asmem);

    const int q0 = blockIdx.x * AQ;
    const int h  = blockIdx.y;
    const int b  = blockIdx.z;
    const int tid = threadIdx.x;
    const int warp = tid >> 5;
    const int lane = tid & 31;
    const int q = lane & 3;
    const int grp = lane >> 3;
    const float c_scale = 0.18033688011112042f;  // 0.125 * log2(e)

    const __half* base  = kqvh + (size_t)b * TT * C3 + (size_t)h * DD;
    const __half* qbase = base + CC;
    const __half* kbase = base;
    const __half* vbase = base + 2 * CC;

    // ---- Prologue: cp.async Q (group 0), KV tile 0 (group 1), tile 1 (g2) ----
#pragma unroll
    for (int i = 0; i < 4; i++) {
        const int c = tid + i * 256;     // 0..1023
        const int r = c >> 3;
        const int c8 = c & 7;
        cp16(sb + SWZ128((uint32_t)(r * 128 + c8 * 16)),
             qbase + (size_t)(q0 + r) * C3 + c8 * 8);
    }
    cp_commit();
    attn_fill(sb + 16384, sb + 16384 + 8192, kbase, vbase, 0, tid);
    cp_commit();
    attn_fill(sb + 32768, sb + 32768 + 8192, kbase, vbase, AK, tid);
    cp_commit();

    cp_wait<2>();       // Q ready
    __syncthreads();

    // ---- Q A-frags (4 k-steps x 4 regs) via ldmatrix.x4 ----
    uint32_t aq_[4][4];
#pragma unroll
    for (int ks = 0; ks < 4; ks++) {
        const uint32_t addr = sb + SWZ128(
            (uint32_t)((16 * warp + (lane & 15)) * 128 + ks * 32 + ((lane >> 4) & 1) * 16));
        ldsm4(aq_[ks], addr);
    }

    const int r0 = warp * 16 + (lane >> 2);
    const int r1 = r0 + 8;

    float oacc[8][4];
#pragma unroll
    for (int nt = 0; nt < 8; nt++)
#pragma unroll
        for (int e = 0; e < 4; e++) oacc[nt][e] = 0.0f;
    float m0 = -1e20f, m1 = -1e20f, l0 = 0.0f, l1 = 0.0f;

    const int ntiles = (q0 + AQ) / AK;   // >= 2

    for (int t = 0; t < ntiles; t++) {
        const int s = t & 1;
        const int j0 = t * AK;
        cp_wait<1>();
        __syncthreads();

        const bool active = (j0 <= q0 + warp * 16 + 15);  // warp-uniform
        if (active) {
            const uint32_t sK = sb + 16384 + s * 16384;
            const uint32_t sV = sK + 8192;

            const uint32_t pb0 =
                __ballot_sync(0xffffffffu, padmask[b * TT + j0 + lane] != 0);
            const uint32_t pb1 =
                __ballot_sync(0xffffffffu, padmask[b * TT + j0 + 32 + lane] != 0);

            // ---- S = Q K^T (fp16 MMA, K frags via ldmatrix.x4) ----
            float sacc[8][4];
#pragma unroll
            for (int nt = 0; nt < 8; nt++)
#pragma unroll
                for (int e = 0; e < 4; e++) sacc[nt][e] = 0.0f;
#pragma unroll
            for (int ks = 0; ks < 4; ks++) {
#pragma unroll
                for (int p = 0; p < 4; p++) {
                    uint32_t kf[4];
                    const int row = (2 * p + (grp >> 1)) * 8 + (lane & 7);
                    const uint32_t addr = sK + SWZ128(
                        (uint32_t)(row * 128 + ks * 32 + (grp & 1) * 16));
                    ldsm4(kf, addr);
                    mma_f16(sacc[2 * p],     aq_[ks], kf);
                    mma_f16(sacc[2 * p + 1], aq_[ks], kf + 2);
                }
            }

            // ---- Mask + scale (log2 domain) + row max ----
            const bool fast =
                (j0 + AK - 1 <= q0 + warp * 16) && (pb0 & pb1) == 0xffffffffu;
            float rm0 = -1e30f, rm1 = -1e30f;
            if (fast) {
#pragma unroll
                for (int nt = 0; nt < 8; nt++) {
#pragma unroll
                    for (int e = 0; e < 4; e++) sacc[nt][e] *= c_scale;
                    rm0 = fmaxf(rm0, fmaxf(sacc[nt][0], sacc[nt][1]));
                    rm1 = fmaxf(rm1, fmaxf(sacc[nt][2], sacc[nt][3]));
                }
            } else {
#pragma unroll
                for (int nt = 0; nt < 8; nt++) {
                    const int c0 = nt * 8 + 2 * q;
                    const int c1 = c0 + 1;
                    const bool p0v = (((c0 < 32 ? pb0 : pb1) >> (c0 & 31)) & 1u) != 0;
                    const bool p1v = (((c1 < 32 ? pb0 : pb1) >> (c1 & 31)) & 1u) != 0;
                    const int k0g = j0 + c0, k1g = j0 + c1;
                    sacc[nt][0] = (p0v && k0g <= q0 + r0) ? sacc[nt][0] * c_scale : -1e30f;
                    sacc[nt][1] = (p1v && k1g <= q0 + r0) ? sacc[nt][1] * c_scale : -1e30f;
                    sacc[nt][2] = (p0v && k0g <= q0 + r1) ? sacc[nt][2] * c_scale : -1e30f;
                    sacc[nt][3] = (p1v && k1g <= q0 + r1) ? sacc[nt][3] * c_scale : -1e30f;
                    rm0 = fmaxf(rm0, fmaxf(sacc[nt][0], sacc[nt][1]));
                    rm1 = fmaxf(rm1, fmaxf(sacc[nt][2], sacc[nt][3]));
                }
            }
            rm0 = fmaxf(rm0, __shfl_xor_sync(0xffffffffu, rm0, 1));
            rm0 = fmaxf(rm0, __shfl_xor_sync(0xffffffffu, rm0, 2));
            rm1 = fmaxf(rm1, __shfl_xor_sync(0xffffffffu, rm1, 1));
            rm1 = fmaxf(rm1, __shfl_xor_sync(0xffffffffu, rm1, 2));

            const float mn0 = fmaxf(m0, rm0);
            const float mn1 = fmaxf(m1, rm1);
            const float alpha0 = exp2f(m0 - mn0);
            const float alpha1 = exp2f(m1 - mn1);
            m0 = mn0; m1 = mn1;

            float ps0 = 0.0f, ps1 = 0.0f;
#pragma unroll
            for (int nt = 0; nt < 8; nt++) {
                float p0 = exp2f(sacc[nt][0] - m0);
                float p1 = exp2f(sacc[nt][1] - m0);
                float p2 = exp2f(sacc[nt][2] - m1);
                float p3 = exp2f(sacc[nt][3] - m1);
                sacc[nt][0] = p0; sacc[nt][1] = p1;
                sacc[nt][2] = p2; sacc[nt][3] = p3;
                ps0 += p0 + p1; ps1 += p2 + p3;
                oacc[nt][0] *= alpha0; oacc[nt][1] *= alpha0;
                oacc[nt][2] *= alpha1; oacc[nt][3] *= alpha1;
            }
            ps0 += __shfl_xor_sync(0xffffffffu, ps0, 1);
            ps0 += __shfl_xor_sync(0xffffffffu, ps0, 2);
            ps1 += __shfl_xor_sync(0xffffffffu, ps1, 1);
            ps1 += __shfl_xor_sync(0xffffffffu, ps1, 2);
            l0 = l0 * alpha0 + ps0;
            l1 = l1 * alpha1 + ps1;

            // ---- O += P V : A-frags by packing sacc pairs; V via ldsm.trans ----
#pragma unroll
            for (int kc = 0; kc < 4; kc++) {
                uint32_t pa[4];
                pa[0] = packh2(sacc[2 * kc][0],     sacc[2 * kc][1]);
                pa[1] = packh2(sacc[2 * kc][2],     sacc[2 * kc][3]);
                pa[2] = packh2(sacc[2 * kc + 1][0], sacc[2 * kc + 1][1]);
                pa[3] = packh2(sacc[2 * kc + 1][2], sacc[2 * kc + 1][3]);
#pragma unroll
                for (int p = 0; p < 4; p++) {
                    uint32_t vf[4];
                    const int row = kc * 16 + (grp & 1) * 8 + (lane & 7);
                    const int c16 = 2 * p + (grp >> 1);
                    const uint32_t addr = sV + SWZ128((uint32_t)(row * 128 + c16 * 16));
                    ldsm4t(vf, addr);
                    mma_f16(oacc[2 * p],     pa, vf);
                    mma_f16(oacc[2 * p + 1], pa, vf + 2);
                }
            }
        }
        __syncthreads();   // all warps done with stage s before refill

        if (t + 2 < ntiles)
            attn_fill(sb + 16384 + s * 16384, sb + 16384 + s * 16384 + 8192,
                      kbase, vbase, (t + 2) * AK, tid);
        cp_commit();
    }

    // ---- Epilogue: normalize + store y (tf32-rounded for proj GEMM) ----
    {
        const float inv0 = 1.0f / l0;
        const float inv1 = 1.0f / l1;
        float* y0 = y + ((size_t)b * TT + q0 + r0) * CC + h * DD;
        float* y1 = y + ((size_t)b * TT + q0 + r1) * CC + h * DD;
#pragma unroll
        for (int nt = 0; nt < 8; nt++) {
            const int c = nt * 8 + 2 * q;
            float2 v0, v1;
            v0.x = __uint_as_float(f2tf32(oacc[nt][0] * inv0));
            v0.y = __uint_as_float(f2tf32(oacc[nt][1] * inv0));
            v1.x = __uint_as_float(f2tf32(oacc[nt][2] * inv1));
            v1.y = __uint_as_float(f2tf32(oacc[nt][3] * inv1));
            *(float2*)(y0 + c) = v0;
            *(float2*)(y1 + c) = v1;
        }
    }
}

// ---------------------------------------------------------------------------
extern "C" void kernel_launch(void* const* d_in, const int* in_sizes, int n_in,
                              void* d_out, int out_size)
{
    const float* x      = (const float*)d_in[0];
    const float* W_kqv  = (const float*)d_in[1];
    const float* b_kqv  = (const float*)d_in[2];
    const float* W_proj = (const float*)d_in[3];
    const float* b_proj = (const float*)d_in[4];
    const int*   pad    = (const int*)d_in[5];
    float* out = (float*)d_out;

    __half* kqvh_ptr;
    float *y_ptr, *xr_ptr, *wk_ptr, *wp_ptr;
    cudaGetSymbolAddress((void**)&kqvh_ptr, g_kqvh);
    cudaGetSymbolAddress((void**)&y_ptr, g_y);
    cudaGetSymbolAddress((void**)&xr_ptr, g_xr);
    cudaGetSymbolAddress((void**)&wk_ptr, g_wk);
    cudaGetSymbolAddress((void**)&wp_ptr, g_wp);

    const int M = BB * TT;  // 8192

    cudaFuncSetAttribute(gemm_tf32_bias,
                         cudaFuncAttributeMaxDynamicSharedMemorySize, GSMEM);
    cudaFuncSetAttribute(attn_kernel,
                         cudaFuncAttributeMaxDynamicSharedMemorySize, ASMEM);

    // 0) Prep: round x and weights to tf32
    round_copy<<<(M * CC) / 1024, 256>>>(x, xr_ptr);
    round_copy<<<(CC * C3) / 1024, 256>>>(W_kqv, wk_ptr);
    round_copy<<<(CC * CC) / 1024, 256>>>(W_proj, wp_ptr);

    // 1) kqv = x @ W_kqv + b_kqv  [8192, 3072], fp16 output for attention
    {
        dim3 grid(C3 / 256, M / 128);
        gemm_tf32_bias<<<grid, 256, GSMEM>>>(xr_ptr, wk_ptr, b_kqv, kqvh_ptr, C3, 1);
    }
    // 2) flash attention (fp16 MMA) -> y  [8192, 1024]
    {
        dim3 grid(TT / AQ, HH, BB);
        attn_kernel<<<grid, 256, ASMEM>>>(kqvh_ptr, pad, y_ptr);
    }
    // 3) out = y @ W_proj + b_proj  [8192, 1024], fp32 output
    {
        dim3 grid(CC / 256, M / 128);
        gemm_tf32_bias<<<grid, 256, GSMEM>>>(y_ptr, wp_ptr, b_proj, out, CC, 0);
    }
}

// round 13
// speedup vs baseline: 8.9173x; 1.5046x over previous
#include <cuda_runtime.h>
#include <cuda_fp16.h>
#include <cstdint>
#include <cstddef>

// Problem constants
#define BB 4
#define TT 2048
#define CC 1024
#define HH 16
#define DD 64
#define C3 (3 * CC)
#define GK 1024   // K of both dense GEMMs

// Scratch (allocation-free rule: __device__ globals)
__device__ __half g_kqvh[(size_t)BB * TT * C3]; // [B,T,3C] (k|q|v) fp16
__device__ __half g_yh[(size_t)BB * TT * CC];   // [B,T,C] fp16
__device__ __half g_xh[(size_t)BB * TT * CC];   // x fp16
__device__ __half g_wkh[(size_t)CC * C3];       // W_kqv fp16, natural [K,N]
__device__ __half g_wph[(size_t)CC * CC];       // W_proj fp16, natural [K,N]

// ---------------------------------------------------------------------------
// Helpers
// ---------------------------------------------------------------------------
__device__ __forceinline__ uint32_t packh2(float lo, float hi) {
    uint32_t r;
    asm("cvt.rn.f16x2.f32 %0, %1, %2;" : "=r"(r) : "f"(hi), "f"(lo));
    return r;
}
__device__ __forceinline__ void mma_f16(float* d, const uint32_t* a, const uint32_t* b) {
    asm volatile(
        "mma.sync.aligned.m16n8k16.row.col.f32.f16.f16.f32 "
        "{%0,%1,%2,%3}, {%4,%5,%6,%7}, {%8,%9}, {%0,%1,%2,%3};"
        : "+f"(d[0]), "+f"(d[1]), "+f"(d[2]), "+f"(d[3])
        : "r"(a[0]), "r"(a[1]), "r"(a[2]), "r"(a[3]), "r"(b[0]), "r"(b[1]));
}
__device__ __forceinline__ void ldsm4(uint32_t* r, uint32_t addr) {
    asm volatile("ldmatrix.sync.aligned.m8n8.x4.shared.b16 {%0,%1,%2,%3}, [%4];"
                 : "=r"(r[0]), "=r"(r[1]), "=r"(r[2]), "=r"(r[3]) : "r"(addr));
}
__device__ __forceinline__ void ldsm4t(uint32_t* r, uint32_t addr) {
    asm volatile("ldmatrix.sync.aligned.m8n8.x4.trans.shared.b16 {%0,%1,%2,%3}, [%4];"
                 : "=r"(r[0]), "=r"(r[1]), "=r"(r[2]), "=r"(r[3]) : "r"(addr));
}
__device__ __forceinline__ uint32_t smem_u32(const void* p) {
    return (uint32_t)__cvta_generic_to_shared(p);
}
__device__ __forceinline__ void cp16(uint32_t s, const void* g) {
    asm volatile("cp.async.cg.shared.global [%0], [%1], 16;" :: "r"(s), "l"(g));
}
__device__ __forceinline__ void cp_commit() {
    asm volatile("cp.async.commit_group;" ::: "memory");
}
template <int n>
__device__ __forceinline__ void cp_wait() {
    asm volatile("cp.async.wait_group %0;" :: "n"(n) : "memory");
}

#define SWZ128(o) ((o) ^ (((o) >> 3) & 0x70))

// ---------------------------------------------------------------------------
// Prep: fp32 -> fp16 copy (1024 elems per block)
// ---------------------------------------------------------------------------
__global__ void half_copy(const float* __restrict__ in, __half* __restrict__ out) {
    const int i = (blockIdx.x * 256 + threadIdx.x) * 4;
    float4 v = *(const float4*)(in + i);
    uint2 o;
    o.x = packh2(v.x, v.y);
    o.y = packh2(v.z, v.w);
    *(uint2*)(out + i) = o;
}

// ---------------------------------------------------------------------------
// FP16 m16n8k16 GEMM with bias: C[M,N] = A[M,1024] @ B[1024,N] + bias[N]
// CTA tile 128x256, BK=64, 256 threads (8 warps), warp tile 64x64.
// A: [128][64] fp16, 128B rows, SW128 (Q pattern).  A-frags via ldsm4.
// B: [64][256] fp16 natural, 512B rows, chunk-swizzle c16^(k&7); B-frags
//    via ldsm4.trans (V pattern).  cp.async double-buffered.
// smem: A stages 2x16KB @0, B stages 2x32KB @32768 = 96KB.
// ---------------------------------------------------------------------------
#define SMA(s) ((s) * 16384)
#define SMB(s) (32768 + (s) * 32768)
#define GSMEM  98304

__device__ __forceinline__ void gemm_copy_tile(
    uint32_t sb, int s, const __half* __restrict__ A, const __half* __restrict__ B,
    int bm, int bn, int k0, int N, int tid)
{
#pragma unroll
    for (int i = 0; i < 4; i++) {
        const int c = tid + i * 256;      // 0..1023
        const int row = c >> 3;           // 0..127
        const int c8 = c & 7;             // 16B chunk in 128B row
        cp16(sb + SMA(s) + SWZ128((uint32_t)(row * 128 + c8 * 16)),
             A + (size_t)(bm + row) * GK + k0 + c8 * 8);
    }
#pragma unroll
    for (int i = 0; i < 8; i++) {
        const int c = tid + i * 256;      // 0..2047
        const int k = c >> 5;             // 0..63
        const int c16 = c & 31;           // 16B chunk in 512B row
        cp16(sb + SMB(s) + k * 512 + ((uint32_t)(c16 ^ (k & 7)) << 4),
             B + (size_t)(k0 + k) * N + bn + c16 * 8);
    }
}

__global__ void __launch_bounds__(256, 1) gemm_f16_bias(
    const __half* __restrict__ A, const __half* __restrict__ Bm,
    const float* __restrict__ bias, void* __restrict__ Cm, int N, int half_out)
{
    extern __shared__ char smem[];
    const uint32_t sb = smem_u32(smem);
    const int tid  = threadIdx.x;
    const int warp = tid >> 5;
    const int lane = tid & 31;
    const int grp  = lane >> 3;
    const int bm = blockIdx.y * 128;
    const int bn = blockIdx.x * 256;

    const int warpM = (warp >> 2) * 64;   // 0 or 64
    const int warpN = (warp & 3) * 64;    // 0,64,128,192
    const int wN16  = warpN >> 3;         // warp's base 16B chunk in B rows

    float acc[4][8][4];
#pragma unroll
    for (int i = 0; i < 4; i++)
#pragma unroll
        for (int j = 0; j < 8; j++)
#pragma unroll
            for (int e = 0; e < 4; e++) acc[i][j][e] = 0.0f;

    gemm_copy_tile(sb, 0, A, Bm, bm, bn, 0, N, tid);
    cp_commit();
    gemm_copy_tile(sb, 1, A, Bm, bm, bn, 64, N, tid);
    cp_commit();

    const int NT = GK / 64;  // 16
    for (int t = 0; t < NT; t++) {
        const int s = t & 1;
        cp_wait<1>();
        __syncthreads();

        const uint32_t sA = sb + SMA(s);
        const uint32_t sB = sb + SMB(s);
#pragma unroll
        for (int ks = 0; ks < 4; ks++) {
            uint32_t af[4][4];
#pragma unroll
            for (int mt = 0; mt < 4; mt++) {
                const int row = warpM + mt * 16 + (lane & 15);
                ldsm4(af[mt], sA + SWZ128(
                    (uint32_t)(row * 128 + ks * 32 + ((lane >> 4) & 1) * 16)));
            }
#pragma unroll
            for (int p = 0; p < 4; p++) {
                uint32_t bf[4];
                const int k = ks * 16 + (grp & 1) * 8 + (lane & 7);
                const int c16 = wN16 + 2 * p + (grp >> 1);
                ldsm4t(bf, sB + k * 512 + ((uint32_t)(c16 ^ (k & 7)) << 4));
#pragma unroll
                for (int mt = 0; mt < 4; mt++) {
                    mma_f16(acc[mt][2 * p],     af[mt], bf);
                    mma_f16(acc[mt][2 * p + 1], af[mt], bf + 2);
                }
            }
        }
        __syncthreads();

        if (t + 2 < NT) {
            gemm_copy_tile(sb, s, A, Bm, bm, bn, (t + 2) * 64, N, tid);
            cp_commit();
        }
    }

    // Epilogue: C = acc + bias
    const int lr = lane >> 2, c2 = (lane & 3) * 2;
#pragma unroll
    for (int mt = 0; mt < 4; mt++) {
#pragma unroll
        for (int nt = 0; nt < 8; nt++) {
            const int grow = bm + warpM + mt * 16 + lr;
            const int gcol = bn + warpN + nt * 8 + c2;
            const float b0 = bias[gcol];
            const float b1 = bias[gcol + 1];
            const float v00 = acc[mt][nt][0] + b0;
            const float v01 = acc[mt][nt][1] + b1;
            const float v10 = acc[mt][nt][2] + b0;
            const float v11 = acc[mt][nt][3] + b1;
            if (half_out) {
                uint32_t* co = (uint32_t*)Cm;
                co[((size_t)grow * N + gcol) >> 1]       = packh2(v00, v01);
                co[((size_t)(grow + 8) * N + gcol) >> 1] = packh2(v10, v11);
            } else {
                float* cf = (float*)Cm;
                *(float2*)(cf + (size_t)grow * N + gcol)       = make_float2(v00, v01);
                *(float2*)(cf + (size_t)(grow + 8) * N + gcol) = make_float2(v10, v11);
            }
        }
    }
}

// ---------------------------------------------------------------------------
// Flash attention v5 (R12, validated): fp16 m16n8k16 + ldmatrix, BQ=128,
// BK=64, register softmax. Epilogue now writes fp16 y.
// ---------------------------------------------------------------------------
#define AQ 128
#define AK 64
#define ASMEM 49152

__device__ __forceinline__ void attn_fill(
    uint32_t sK, uint32_t sV, const __half* __restrict__ kb,
    const __half* __restrict__ vb, int j0, int tid)
{
#pragma unroll
    for (int i = 0; i < 4; i++) {
        const int cc = tid + (i & 1) * 256;   // 0..511
        const int j = cc >> 3;
        const int c8 = cc & 7;
        const uint32_t off = SWZ128((uint32_t)(j * 128 + c8 * 16));
        if (i < 2) cp16(sK + off, kb + (size_t)(j0 + j) * C3 + c8 * 8);
        else       cp16(sV + off, vb + (size_t)(j0 + j) * C3 + c8 * 8);
    }
}

__global__ void __launch_bounds__(256) attn_kernel(
    const __half* __restrict__ kqvh, const int* __restrict__ padmask,
    __half* __restrict__ y)
{
    extern __shared__ char asmem[];
    const uint32_t sb = smem_u32(asmem);

    const int q0 = blockIdx.x * AQ;
    const int h  = blockIdx.y;
    const int b  = blockIdx.z;
    const int tid = threadIdx.x;
    const int warp = tid >> 5;
    const int lane = tid & 31;
    const int q = lane & 3;
    const int grp = lane >> 3;
    const float c_scale = 0.18033688011112042f;  // 0.125 * log2(e)

    const __half* base  = kqvh + (size_t)b * TT * C3 + (size_t)h * DD;
    const __half* qbase = base + CC;
    const __half* kbase = base;
    const __half* vbase = base + 2 * CC;

    // ---- Prologue: cp.async Q, KV tile 0, KV tile 1 ----
#pragma unroll
    for (int i = 0; i < 4; i++) {
        const int c = tid + i * 256;
        const int r = c >> 3;
        const int c8 = c & 7;
        cp16(sb + SWZ128((uint32_t)(r * 128 + c8 * 16)),
             qbase + (size_t)(q0 + r) * C3 + c8 * 8);
    }
    cp_commit();
    attn_fill(sb + 16384, sb + 16384 + 8192, kbase, vbase, 0, tid);
    cp_commit();
    attn_fill(sb + 32768, sb + 32768 + 8192, kbase, vbase, AK, tid);
    cp_commit();

    cp_wait<2>();
    __syncthreads();

    uint32_t aq_[4][4];
#pragma unroll
    for (int ks = 0; ks < 4; ks++) {
        const uint32_t addr = sb + SWZ128(
            (uint32_t)((16 * warp + (lane & 15)) * 128 + ks * 32 + ((lane >> 4) & 1) * 16));
        ldsm4(aq_[ks], addr);
    }

    const int r0 = warp * 16 + (lane >> 2);
    const int r1 = r0 + 8;

    float oacc[8][4];
#pragma unroll
    for (int nt = 0; nt < 8; nt++)
#pragma unroll
        for (int e = 0; e < 4; e++) oacc[nt][e] = 0.0f;
    float m0 = -1e20f, m1 = -1e20f, l0 = 0.0f, l1 = 0.0f;

    const int ntiles = (q0 + AQ) / AK;

    for (int t = 0; t < ntiles; t++) {
        const int s = t & 1;
        const int j0 = t * AK;
        cp_wait<1>();
        __syncthreads();

        const bool active = (j0 <= q0 + warp * 16 + 15);
        if (active) {
            const uint32_t sK = sb + 16384 + s * 16384;
            const uint32_t sV = sK + 8192;

            const uint32_t pb0 =
                __ballot_sync(0xffffffffu, padmask[b * TT + j0 + lane] != 0);
            const uint32_t pb1 =
                __ballot_sync(0xffffffffu, padmask[b * TT + j0 + 32 + lane] != 0);

            float sacc[8][4];
#pragma unroll
            for (int nt = 0; nt < 8; nt++)
#pragma unroll
                for (int e = 0; e < 4; e++) sacc[nt][e] = 0.0f;
#pragma unroll
            for (int ks = 0; ks < 4; ks++) {
#pragma unroll
                for (int p = 0; p < 4; p++) {
                    uint32_t kf[4];
                    const int row = (2 * p + (grp >> 1)) * 8 + (lane & 7);
                    const uint32_t addr = sK + SWZ128(
                        (uint32_t)(row * 128 + ks * 32 + (grp & 1) * 16));
                    ldsm4(kf, addr);
                    mma_f16(sacc[2 * p],     aq_[ks], kf);
                    mma_f16(sacc[2 * p + 1], aq_[ks], kf + 2);
                }
            }

            const bool fast =
                (j0 + AK - 1 <= q0 + warp * 16) && (pb0 & pb1) == 0xffffffffu;
            float rm0 = -1e30f, rm1 = -1e30f;
            if (fast) {
#pragma unroll
                for (int nt = 0; nt < 8; nt++) {
#pragma unroll
                    for (int e = 0; e < 4; e++) sacc[nt][e] *= c_scale;
                    rm0 = fmaxf(rm0, fmaxf(sacc[nt][0], sacc[nt][1]));
                    rm1 = fmaxf(rm1, fmaxf(sacc[nt][2], sacc[nt][3]));
                }
            } else {
#pragma unroll
                for (int nt = 0; nt < 8; nt++) {
                    const int c0 = nt * 8 + 2 * q;
                    const int c1 = c0 + 1;
                    const bool p0v = (((c0 < 32 ? pb0 : pb1) >> (c0 & 31)) & 1u) != 0;
                    const bool p1v = (((c1 < 32 ? pb0 : pb1) >> (c1 & 31)) & 1u) != 0;
                    const int k0g = j0 + c0, k1g = j0 + c1;
                    sacc[nt][0] = (p0v && k0g <= q0 + r0) ? sacc[nt][0] * c_scale : -1e30f;
                    sacc[nt][1] = (p1v && k1g <= q0 + r0) ? sacc[nt][1] * c_scale : -1e30f;
                    sacc[nt][2] = (p0v && k0g <= q0 + r1) ? sacc[nt][2] * c_scale : -1e30f;
                    sacc[nt][3] = (p1v && k1g <= q0 + r1) ? sacc[nt][3] * c_scale : -1e30f;
                    rm0 = fmaxf(rm0, fmaxf(sacc[nt][0], sacc[nt][1]));
                    rm1 = fmaxf(rm1, fmaxf(sacc[nt][2], sacc[nt][3]));
                }
            }
            rm0 = fmaxf(rm0, __shfl_xor_sync(0xffffffffu, rm0, 1));
            rm0 = fmaxf(rm0, __shfl_xor_sync(0xffffffffu, rm0, 2));
            rm1 = fmaxf(rm1, __shfl_xor_sync(0xffffffffu, rm1, 1));
            rm1 = fmaxf(rm1, __shfl_xor_sync(0xffffffffu, rm1, 2));

            const float mn0 = fmaxf(m0, rm0);
            const float mn1 = fmaxf(m1, rm1);
            const float alpha0 = exp2f(m0 - mn0);
            const float alpha1 = exp2f(m1 - mn1);
            m0 = mn0; m1 = mn1;

            float ps0 = 0.0f, ps1 = 0.0f;
#pragma unroll
            for (int nt = 0; nt < 8; nt++) {
                float p0 = exp2f(sacc[nt][0] - m0);
                float p1 = exp2f(sacc[nt][1] - m0);
                float p2 = exp2f(sacc[nt][2] - m1);
                float p3 = exp2f(sacc[nt][3] - m1);
                sacc[nt][0] = p0; sacc[nt][1] = p1;
                sacc[nt][2] = p2; sacc[nt][3] = p3;
                ps0 += p0 + p1; ps1 += p2 + p3;
                oacc[nt][0] *= alpha0; oacc[nt][1] *= alpha0;
                oacc[nt][2] *= alpha1; oacc[nt][3] *= alpha1;
            }
            ps0 += __shfl_xor_sync(0xffffffffu, ps0, 1);
            ps0 += __shfl_xor_sync(0xffffffffu, ps0, 2);
            ps1 += __shfl_xor_sync(0xffffffffu, ps1, 1);
            ps1 += __shfl_xor_sync(0xffffffffu, ps1, 2);
            l0 = l0 * alpha0 + ps0;
            l1 = l1 * alpha1 + ps1;

#pragma unroll
            for (int kc = 0; kc < 4; kc++) {
                uint32_t pa[4];
                pa[0] = packh2(sacc[2 * kc][0],     sacc[2 * kc][1]);
                pa[1] = packh2(sacc[2 * kc][2],     sacc[2 * kc][3]);
                pa[2] = packh2(sacc[2 * kc + 1][0], sacc[2 * kc + 1][1]);
                pa[3] = packh2(sacc[2 * kc + 1][2], sacc[2 * kc + 1][3]);
#pragma unroll
                for (int p = 0; p < 4; p++) {
                    uint32_t vf[4];
                    const int row = kc * 16 + (grp & 1) * 8 + (lane & 7);
                    const int c16 = 2 * p + (grp >> 1);
                    const uint32_t addr = sV + SWZ128((uint32_t)(row * 128 + c16 * 16));
                    ldsm4t(vf, addr);
                    mma_f16(oacc[2 * p],     pa, vf);
                    mma_f16(oacc[2 * p + 1], pa, vf + 2);
                }
            }
        }
        __syncthreads();

        if (t + 2 < ntiles)
            attn_fill(sb + 16384 + s * 16384, sb + 16384 + s * 16384 + 8192,
                      kbase, vbase, (t + 2) * AK, tid);
        cp_commit();
    }

    // ---- Epilogue: normalize + store fp16 y ----
    {
        const float inv0 = 1.0f / l0;
        const float inv1 = 1.0f / l1;
        uint32_t* yw = (uint32_t*)y;
        const size_t o0 = ((size_t)b * TT + q0 + r0) * CC + h * DD;
        const size_t o1 = ((size_t)b * TT + q0 + r1) * CC + h * DD;
#pragma unroll
        for (int nt = 0; nt < 8; nt++) {
            const int c = nt * 8 + 2 * q;
            yw[(o0 + c) >> 1] = packh2(oacc[nt][0] * inv0, oacc[nt][1] * inv0);
            yw[(o1 + c) >> 1] = packh2(oacc[nt][2] * inv1, oacc[nt][3] * inv1);
        }
    }
}

// ---------------------------------------------------------------------------
extern "C" void kernel_launch(void* const* d_in, const int* in_sizes, int n_in,
                              void* d_out, int out_size)
{
    const float* x      = (const float*)d_in[0];
    const float* W_kqv  = (const float*)d_in[1];
    const float* b_kqv  = (const float*)d_in[2];
    const float* W_proj = (const float*)d_in[3];
    const float* b_proj = (const float*)d_in[4];
    const int*   pad    = (const int*)d_in[5];
    float* out = (float*)d_out;

    __half *kqvh_ptr, *yh_ptr, *xh_ptr, *wkh_ptr, *wph_ptr;
    cudaGetSymbolAddress((void**)&kqvh_ptr, g_kqvh);
    cudaGetSymbolAddress((void**)&yh_ptr, g_yh);
    cudaGetSymbolAddress((void**)&xh_ptr, g_xh);
    cudaGetSymbolAddress((void**)&wkh_ptr, g_wkh);
    cudaGetSymbolAddress((void**)&wph_ptr, g_wph);

    const int M = BB * TT;  // 8192

    cudaFuncSetAttribute(gemm_f16_bias,
                         cudaFuncAttributeMaxDynamicSharedMemorySize, GSMEM);
    cudaFuncSetAttribute(attn_kernel,
                         cudaFuncAttributeMaxDynamicSharedMemorySize, ASMEM);

    // 0) Prep: convert x and weights to fp16
    half_copy<<<(M * CC) / 1024, 256>>>(x, xh_ptr);
    half_copy<<<(CC * C3) / 1024, 256>>>(W_kqv, wkh_ptr);
    half_copy<<<(CC * CC) / 1024, 256>>>(W_proj, wph_ptr);

    // 1) kqv = x @ W_kqv + b_kqv  [8192, 3072], fp16 output
    {
        dim3 grid(C3 / 256, M / 128);
        gemm_f16_bias<<<grid, 256, GSMEM>>>(xh_ptr, wkh_ptr, b_kqv, kqvh_ptr, C3, 1);
    }
    // 2) flash attention (fp16 MMA) -> y fp16  [8192, 1024]
    {
        dim3 grid(TT / AQ, HH, BB);
        attn_kernel<<<grid, 256, ASMEM>>>(kqvh_ptr, pad, yh_ptr);
    }
    // 3) out = y @ W_proj + b_proj  [8192, 1024], fp32 output
    {
        dim3 grid(CC / 256, M / 128);
        gemm_f16_bias<<<grid, 256, GSMEM>>>(yh_ptr, wph_ptr, b_proj, out, CC, 0);
    }
}

// round 14
// speedup vs baseline: 8.9992x; 1.0092x over previous
#include <cuda_runtime.h>
#include <cuda_fp16.h>
#include <cstdint>
#include <cstddef>

// Problem constants
#define BB 4
#define TT 2048
#define CC 1024
#define HH 16
#define DD 64
#define C3 (3 * CC)
#define GK 1024   // K of both dense GEMMs

// Scratch (allocation-free rule: __device__ globals)
__device__ __half g_kqvh[(size_t)BB * TT * C3]; // [B,T,3C] (k|q|v) fp16
__device__ __half g_yh[(size_t)BB * TT * CC];   // [B,T,C] fp16
__device__ __half g_xh[(size_t)BB * TT * CC];   // x fp16
__device__ __half g_wkh[(size_t)CC * C3];       // W_kqv fp16, natural [K,N]
__device__ __half g_wph[(size_t)CC * CC];       // W_proj fp16, natural [K,N]

// ---------------------------------------------------------------------------
// Helpers
// ---------------------------------------------------------------------------
__device__ __forceinline__ uint32_t packh2(float lo, float hi) {
    uint32_t r;
    asm("cvt.rn.f16x2.f32 %0, %1, %2;" : "=r"(r) : "f"(hi), "f"(lo));
    return r;
}
__device__ __forceinline__ uint32_t hex2(uint32_t a) {
    uint32_t r;
    asm("ex2.approx.f16x2 %0, %1;" : "=r"(r) : "r"(a));
    return r;
}
__device__ __forceinline__ uint32_t hadd2(uint32_t a, uint32_t b) {
    uint32_t r;
    asm("add.rn.f16x2 %0, %1, %2;" : "=r"(r) : "r"(a), "r"(b));
    return r;
}
__device__ __forceinline__ float2 h22f2(uint32_t u) {
    __half2 h = *reinterpret_cast<__half2*>(&u);
    return __half22float2(h);
}
__device__ __forceinline__ void mma_f16(float* d, const uint32_t* a, const uint32_t* b) {
    asm volatile(
        "mma.sync.aligned.m16n8k16.row.col.f32.f16.f16.f32 "
        "{%0,%1,%2,%3}, {%4,%5,%6,%7}, {%8,%9}, {%0,%1,%2,%3};"
        : "+f"(d[0]), "+f"(d[1]), "+f"(d[2]), "+f"(d[3])
        : "r"(a[0]), "r"(a[1]), "r"(a[2]), "r"(a[3]), "r"(b[0]), "r"(b[1]));
}
__device__ __forceinline__ void ldsm4(uint32_t* r, uint32_t addr) {
    asm volatile("ldmatrix.sync.aligned.m8n8.x4.shared.b16 {%0,%1,%2,%3}, [%4];"
                 : "=r"(r[0]), "=r"(r[1]), "=r"(r[2]), "=r"(r[3]) : "r"(addr));
}
__device__ __forceinline__ void ldsm4t(uint32_t* r, uint32_t addr) {
    asm volatile("ldmatrix.sync.aligned.m8n8.x4.trans.shared.b16 {%0,%1,%2,%3}, [%4];"
                 : "=r"(r[0]), "=r"(r[1]), "=r"(r[2]), "=r"(r[3]) : "r"(addr));
}
__device__ __forceinline__ uint32_t smem_u32(const void* p) {
    return (uint32_t)__cvta_generic_to_shared(p);
}
__device__ __forceinline__ void cp16(uint32_t s, const void* g) {
    asm volatile("cp.async.cg.shared.global [%0], [%1], 16;" :: "r"(s), "l"(g));
}
__device__ __forceinline__ void cp_commit() {
    asm volatile("cp.async.commit_group;" ::: "memory");
}
template <int n>
__device__ __forceinline__ void cp_wait() {
    asm volatile("cp.async.wait_group %0;" :: "n"(n) : "memory");
}

#define SWZ128(o) ((o) ^ (((o) >> 3) & 0x70))

// ---------------------------------------------------------------------------
// Prep: fp32 -> fp16 copy (1024 elems per block)
// ---------------------------------------------------------------------------
__global__ void half_copy(const float* __restrict__ in, __half* __restrict__ out) {
    const int i = (blockIdx.x * 256 + threadIdx.x) * 4;
    float4 v = *(const float4*)(in + i);
    uint2 o;
    o.x = packh2(v.x, v.y);
    o.y = packh2(v.z, v.w);
    *(uint2*)(out + i) = o;
}

// ---------------------------------------------------------------------------
// FP16 m16n8k16 GEMM with bias: C[M,N] = A[M,1024] @ B[1024,N] + bias[N]
// CTA tile 128x256, BK=64, 256 threads (8 warps), warp tile 64x64.
// 3-stage cp.async ring, ONE __syncthreads per K-tile (refill target is the
// stage computed last iteration, protected by this iteration's barrier).
// smem: A stages 3x16KB @0, B stages 3x32KB @49152 = 144KB.
// ---------------------------------------------------------------------------
#define SMA(s) ((s) * 16384)
#define SMB(s) (49152 + (s) * 32768)
#define GSMEM  147456

__device__ __forceinline__ void gemm_copy_tile(
    uint32_t sb, int s, const __half* __restrict__ A, const __half* __restrict__ B,
    int bm, int bn, int k0, int N, int tid)
{
#pragma unroll
    for (int i = 0; i < 4; i++) {
        const int c = tid + i * 256;      // 0..1023
        const int row = c >> 3;           // 0..127
        const int c8 = c & 7;             // 16B chunk in 128B row
        cp16(sb + SMA(s) + SWZ128((uint32_t)(row * 128 + c8 * 16)),
             A + (size_t)(bm + row) * GK + k0 + c8 * 8);
    }
#pragma unroll
    for (int i = 0; i < 8; i++) {
        const int c = tid + i * 256;      // 0..2047
        const int k = c >> 5;             // 0..63
        const int c16 = c & 31;           // 16B chunk in 512B row
        cp16(sb + SMB(s) + k * 512 + ((uint32_t)(c16 ^ (k & 7)) << 4),
             B + (size_t)(k0 + k) * N + bn + c16 * 8);
    }
}

__global__ void __launch_bounds__(256, 1) gemm_f16_bias(
    const __half* __restrict__ A, const __half* __restrict__ Bm,
    const float* __restrict__ bias, void* __restrict__ Cm, int N, int half_out)
{
    extern __shared__ char smem[];
    const uint32_t sb = smem_u32(smem);
    const int tid  = threadIdx.x;
    const int warp = tid >> 5;
    const int lane = tid & 31;
    const int grp  = lane >> 3;
    const int bm = blockIdx.y * 128;
    const int bn = blockIdx.x * 256;

    const int warpM = (warp >> 2) * 64;   // 0 or 64
    const int warpN = (warp & 3) * 64;    // 0,64,128,192
    const int wN16  = warpN >> 3;         // warp's base 16B chunk in B rows

    float acc[4][8][4];
#pragma unroll
    for (int i = 0; i < 4; i++)
#pragma unroll
        for (int j = 0; j < 8; j++)
#pragma unroll
            for (int e = 0; e < 4; e++) acc[i][j][e] = 0.0f;

    gemm_copy_tile(sb, 0, A, Bm, bm, bn, 0, N, tid);
    cp_commit();
    gemm_copy_tile(sb, 1, A, Bm, bm, bn, 64, N, tid);
    cp_commit();

    const int NT = GK / 64;  // 16
    for (int t = 0; t < NT; t++) {
        if (t == NT - 1) cp_wait<0>(); else cp_wait<1>();
        __syncthreads();

        // Refill stage (t+2)%3 (computed in iter t-1; barrier above protects it)
        if (t + 2 < NT) {
            gemm_copy_tile(sb, (t + 2) % 3, A, Bm, bm, bn, (t + 2) * 64, N, tid);
            cp_commit();
        }

        const int s = t % 3;
        const uint32_t sA = sb + SMA(s);
        const uint32_t sB = sb + SMB(s);
#pragma unroll
        for (int ks = 0; ks < 4; ks++) {
            uint32_t af[4][4];
#pragma unroll
            for (int mt = 0; mt < 4; mt++) {
                const int row = warpM + mt * 16 + (lane & 15);
                ldsm4(af[mt], sA + SWZ128(
                    (uint32_t)(row * 128 + ks * 32 + ((lane >> 4) & 1) * 16)));
            }
#pragma unroll
            for (int p = 0; p < 4; p++) {
                uint32_t bf[4];
                const int k = ks * 16 + (grp & 1) * 8 + (lane & 7);
                const int c16 = wN16 + 2 * p + (grp >> 1);
                ldsm4t(bf, sB + k * 512 + ((uint32_t)(c16 ^ (k & 7)) << 4));
#pragma unroll
                for (int mt = 0; mt < 4; mt++) {
                    mma_f16(acc[mt][2 * p],     af[mt], bf);
                    mma_f16(acc[mt][2 * p + 1], af[mt], bf + 2);
                }
            }
        }
    }

    // Epilogue: C = acc + bias
    const int lr = lane >> 2, c2 = (lane & 3) * 2;
#pragma unroll
    for (int mt = 0; mt < 4; mt++) {
#pragma unroll
        for (int nt = 0; nt < 8; nt++) {
            const int grow = bm + warpM + mt * 16 + lr;
            const int gcol = bn + warpN + nt * 8 + c2;
            const float b0 = bias[gcol];
            const float b1 = bias[gcol + 1];
            const float v00 = acc[mt][nt][0] + b0;
            const float v01 = acc[mt][nt][1] + b1;
            const float v10 = acc[mt][nt][2] + b0;
            const float v11 = acc[mt][nt][3] + b1;
            if (half_out) {
                uint32_t* co = (uint32_t*)Cm;
                co[((size_t)grow * N + gcol) >> 1]       = packh2(v00, v01);
                co[((size_t)(grow + 8) * N + gcol) >> 1] = packh2(v10, v11);
            } else {
                float* cf = (float*)Cm;
                *(float2*)(cf + (size_t)grow * N + gcol)       = make_float2(v00, v01);
                *(float2*)(cf + (size_t)(grow + 8) * N + gcol) = make_float2(v10, v11);
            }
        }
    }
}

// ---------------------------------------------------------------------------
// Flash attention v6: fp16 m16n8k16 + ldmatrix, BQ=128, BK=64.
// fp16-native softmax: row max on RAW scores, t=fma(s,c,-m) packed to f16x2,
// ex2.approx.f16x2 -> outputs ARE the PV A-fragments. Row sums via HADD2
// tree (depth 2). 3-stage K/V ring, ONE barrier per tile.
// smem: Q 16KB @0; K/V stages s @ 16384+s*16384 (K 8KB + V 8KB). 64KB.
// ---------------------------------------------------------------------------
#define AQ 128
#define AK 64
#define ASMEM 65536

__device__ __forceinline__ void attn_fill(
    uint32_t sK, uint32_t sV, const __half* __restrict__ kb,
    const __half* __restrict__ vb, int j0, int tid)
{
#pragma unroll
    for (int i = 0; i < 4; i++) {
        const int cc = tid + (i & 1) * 256;   // 0..511
        const int j = cc >> 3;
        const int c8 = cc & 7;
        const uint32_t off = SWZ128((uint32_t)(j * 128 + c8 * 16));
        if (i < 2) cp16(sK + off, kb + (size_t)(j0 + j) * C3 + c8 * 8);
        else       cp16(sV + off, vb + (size_t)(j0 + j) * C3 + c8 * 8);
    }
}

__global__ void __launch_bounds__(256) attn_kernel(
    const __half* __restrict__ kqvh, const int* __restrict__ padmask,
    __half* __restrict__ y)
{
    extern __shared__ char asmem[];
    const uint32_t sb = smem_u32(asmem);

    const int q0 = blockIdx.x * AQ;
    const int h  = blockIdx.y;
    const int b  = blockIdx.z;
    const int tid = threadIdx.x;
    const int warp = tid >> 5;
    const int lane = tid & 31;
    const int q = lane & 3;
    const int grp = lane >> 3;
    const float c_scale = 0.18033688011112042f;  // 0.125 * log2(e)

    const __half* base  = kqvh + (size_t)b * TT * C3 + (size_t)h * DD;
    const __half* qbase = base + CC;
    const __half* kbase = base;
    const __half* vbase = base + 2 * CC;

    // ---- Prologue: cp.async Q, KV tiles 0 and 1 ----
#pragma unroll
    for (int i = 0; i < 4; i++) {
        const int c = tid + i * 256;
        const int r = c >> 3;
        const int c8 = c & 7;
        cp16(sb + SWZ128((uint32_t)(r * 128 + c8 * 16)),
             qbase + (size_t)(q0 + r) * C3 + c8 * 8);
    }
    cp_commit();
    attn_fill(sb + 16384, sb + 16384 + 8192, kbase, vbase, 0, tid);
    cp_commit();
    attn_fill(sb + 32768, sb + 32768 + 8192, kbase, vbase, AK, tid);
    cp_commit();

    cp_wait<2>();   // Q ready
    __syncthreads();

    uint32_t aq_[4][4];
#pragma unroll
    for (int ks = 0; ks < 4; ks++) {
        const uint32_t addr = sb + SWZ128(
            (uint32_t)((16 * warp + (lane & 15)) * 128 + ks * 32 + ((lane >> 4) & 1) * 16));
        ldsm4(aq_[ks], addr);
    }

    const int r0 = warp * 16 + (lane >> 2);
    const int r1 = r0 + 8;

    float oacc[8][4];
#pragma unroll
    for (int nt = 0; nt < 8; nt++)
#pragma unroll
        for (int e = 0; e < 4; e++) oacc[nt][e] = 0.0f;
    float m0 = -1e20f, m1 = -1e20f, l0 = 0.0f, l1 = 0.0f;

    const int ntiles = (q0 + AQ) / AK;   // >= 2

    for (int t = 0; t < ntiles; t++) {
        const int j0 = t * AK;
        if (t == ntiles - 1) cp_wait<0>(); else cp_wait<1>();
        __syncthreads();

        // Refill stage (t+2)%3 (computed last iteration; barrier protects)
        if (t + 2 < ntiles) {
            const uint32_t st = sb + 16384 + ((t + 2) % 3) * 16384;
            attn_fill(st, st + 8192, kbase, vbase, (t + 2) * AK, tid);
            cp_commit();
        }

        const bool active = (j0 <= q0 + warp * 16 + 15);  // warp-uniform
        if (active) {
            const uint32_t sK = sb + 16384 + (t % 3) * 16384;
            const uint32_t sV = sK + 8192;

            const uint32_t pb0 =
                __ballot_sync(0xffffffffu, padmask[b * TT + j0 + lane] != 0);
            const uint32_t pb1 =
                __ballot_sync(0xffffffffu, padmask[b * TT + j0 + 32 + lane] != 0);

            // ---- S = Q K^T ----
            float sacc[8][4];
#pragma unroll
            for (int nt = 0; nt < 8; nt++)
#pragma unroll
                for (int e = 0; e < 4; e++) sacc[nt][e] = 0.0f;
#pragma unroll
            for (int ks = 0; ks < 4; ks++) {
#pragma unroll
                for (int p = 0; p < 4; p++) {
                    uint32_t kf[4];
                    const int row = (2 * p + (grp >> 1)) * 8 + (lane & 7);
                    const uint32_t addr = sK + SWZ128(
                        (uint32_t)(row * 128 + ks * 32 + (grp & 1) * 16));
                    ldsm4(kf, addr);
                    mma_f16(sacc[2 * p],     aq_[ks], kf);
                    mma_f16(sacc[2 * p + 1], aq_[ks], kf + 2);
                }
            }

            // ---- Mask (raw domain): invalid -> -1e30 ----
            const bool fast =
                (j0 + AK - 1 <= q0 + warp * 16) && (pb0 & pb1) == 0xffffffffu;
            if (!fast) {
#pragma unroll
                for (int nt = 0; nt < 8; nt++) {
                    const int c0 = nt * 8 + 2 * q;
                    const int c1 = c0 + 1;
                    const bool p0v = (((c0 < 32 ? pb0 : pb1) >> (c0 & 31)) & 1u) != 0;
                    const bool p1v = (((c1 < 32 ? pb0 : pb1) >> (c1 & 31)) & 1u) != 0;
                    const int k0g = j0 + c0, k1g = j0 + c1;
                    if (!(p0v && k0g <= q0 + r0)) sacc[nt][0] = -1e30f;
                    if (!(p1v && k1g <= q0 + r0)) sacc[nt][1] = -1e30f;
                    if (!(p0v && k0g <= q0 + r1)) sacc[nt][2] = -1e30f;
                    if (!(p1v && k1g <= q0 + r1)) sacc[nt][3] = -1e30f;
                }
            }

            // ---- Row max on RAW scores (monotonic; scale applied once) ----
            float rm0 = -1e30f, rm1 = -1e30f;
#pragma unroll
            for (int nt = 0; nt < 8; nt++) {
                rm0 = fmaxf(rm0, fmaxf(sacc[nt][0], sacc[nt][1]));
                rm1 = fmaxf(rm1, fmaxf(sacc[nt][2], sacc[nt][3]));
            }
            rm0 = fmaxf(rm0, __shfl_xor_sync(0xffffffffu, rm0, 1));
            rm0 = fmaxf(rm0, __shfl_xor_sync(0xffffffffu, rm0, 2));
            rm1 = fmaxf(rm1, __shfl_xor_sync(0xffffffffu, rm1, 1));
            rm1 = fmaxf(rm1, __shfl_xor_sync(0xffffffffu, rm1, 2));

            const float mn0 = fmaxf(m0, rm0 * c_scale);
            const float mn1 = fmaxf(m1, rm1 * c_scale);
            const float alpha0 = exp2f(m0 - mn0);
            const float alpha1 = exp2f(m1 - mn1);
            m0 = mn0; m1 = mn1;
            const float nm0 = -m0, nm1 = -m1;

            // ---- exp in packed fp16 (outputs are PV A-fragments) + rescale ----
            uint32_t Pp[8][2];
#pragma unroll
            for (int nt = 0; nt < 8; nt++) {
                const float t00 = fmaf(sacc[nt][0], c_scale, nm0);
                const float t01 = fmaf(sacc[nt][1], c_scale, nm0);
                const float t10 = fmaf(sacc[nt][2], c_scale, nm1);
                const float t11 = fmaf(sacc[nt][3], c_scale, nm1);
                Pp[nt][0] = hex2(packh2(t00, t01));
                Pp[nt][1] = hex2(packh2(t10, t11));
                oacc[nt][0] *= alpha0; oacc[nt][1] *= alpha0;
                oacc[nt][2] *= alpha1; oacc[nt][3] *= alpha1;
            }

            // ---- Row sums: depth-2 HADD2 tree, finish in fp32 ----
            {
                const uint32_t u0 = hadd2(hadd2(Pp[0][0], Pp[1][0]),
                                          hadd2(Pp[2][0], Pp[3][0]));
                const uint32_t u1 = hadd2(hadd2(Pp[4][0], Pp[5][0]),
                                          hadd2(Pp[6][0], Pp[7][0]));
                const uint32_t v0 = hadd2(hadd2(Pp[0][1], Pp[1][1]),
                                          hadd2(Pp[2][1], Pp[3][1]));
                const uint32_t v1 = hadd2(hadd2(Pp[4][1], Pp[5][1]),
                                          hadd2(Pp[6][1], Pp[7][1]));
                const float2 a = h22f2(u0), bb = h22f2(u1);
                const float2 cfv = h22f2(v0), d = h22f2(v1);
                float ps0 = (a.x + a.y) + (bb.x + bb.y);
                float ps1 = (cfv.x + cfv.y) + (d.x + d.y);
                ps0 += __shfl_xor_sync(0xffffffffu, ps0, 1);
                ps0 += __shfl_xor_sync(0xffffffffu, ps0, 2);
                ps1 += __shfl_xor_sync(0xffffffffu, ps1, 1);
                ps1 += __shfl_xor_sync(0xffffffffu, ps1, 2);
                l0 = l0 * alpha0 + ps0;
                l1 = l1 * alpha1 + ps1;
            }

            // ---- O += P V (A-frags = Pp, no packing) ----
#pragma unroll
            for (int kc = 0; kc < 4; kc++) {
                uint32_t pa[4];
                pa[0] = Pp[2 * kc][0];
                pa[1] = Pp[2 * kc][1];
                pa[2] = Pp[2 * kc + 1][0];
                pa[3] = Pp[2 * kc + 1][1];
#pragma unroll
                for (int p = 0; p < 4; p++) {
                    uint32_t vf[4];
                    const int row = kc * 16 + (grp & 1) * 8 + (lane & 7);
                    const int c16 = 2 * p + (grp >> 1);
                    const uint32_t addr = sV + SWZ128((uint32_t)(row * 128 + c16 * 16));
                    ldsm4t(vf, addr);
                    mma_f16(oacc[2 * p],     pa, vf);
                    mma_f16(oacc[2 * p + 1], pa, vf + 2);
                }
            }
        }
    }

    // ---- Epilogue: normalize + store fp16 y ----
    {
        const float inv0 = 1.0f / l0;
        const float inv1 = 1.0f / l1;
        uint32_t* yw = (uint32_t*)y;
        const size_t o0 = ((size_t)b * TT + q0 + r0) * CC + h * DD;
        const size_t o1 = ((size_t)b * TT + q0 + r1) * CC + h * DD;
#pragma unroll
        for (int nt = 0; nt < 8; nt++) {
            const int c = nt * 8 + 2 * q;
            yw[(o0 + c) >> 1] = packh2(oacc[nt][0] * inv0, oacc[nt][1] * inv0);
            yw[(o1 + c) >> 1] = packh2(oacc[nt][2] * inv1, oacc[nt][3] * inv1);
        }
    }
}

// ---------------------------------------------------------------------------
extern "C" void kernel_launch(void* const* d_in, const int* in_sizes, int n_in,
                              void* d_out, int out_size)
{
    const float* x      = (const float*)d_in[0];
    const float* W_kqv  = (const float*)d_in[1];
    const float* b_kqv  = (const float*)d_in[2];
    const float* W_proj = (const float*)d_in[3];
    const float* b_proj = (const float*)d_in[4];
    const int*   pad    = (const int*)d_in[5];
    float* out = (float*)d_out;

    __half *kqvh_ptr, *yh_ptr, *xh_ptr, *wkh_ptr, *wph_ptr;
    cudaGetSymbolAddress((void**)&kqvh_ptr, g_kqvh);
    cudaGetSymbolAddress((void**)&yh_ptr, g_yh);
    cudaGetSymbolAddress((void**)&xh_ptr, g_xh);
    cudaGetSymbolAddress((void**)&wkh_ptr, g_wkh);
    cudaGetSymbolAddress((void**)&wph_ptr, g_wph);

    const int M = BB * TT;  // 8192

    cudaFuncSetAttribute(gemm_f16_bias,
                         cudaFuncAttributeMaxDynamicSharedMemorySize, GSMEM);
    cudaFuncSetAttribute(attn_kernel,
                         cudaFuncAttributeMaxDynamicSharedMemorySize, ASMEM);

    // 0) Prep: convert x and weights to fp16
    half_copy<<<(M * CC) / 1024, 256>>>(x, xh_ptr);
    half_copy<<<(CC * C3) / 1024, 256>>>(W_kqv, wkh_ptr);
    half_copy<<<(CC * CC) / 1024, 256>>>(W_proj, wph_ptr);

    // 1) kqv = x @ W_kqv + b_kqv  [8192, 3072], fp16 output
    {
        dim3 grid(C3 / 256, M / 128);
        gemm_f16_bias<<<grid, 256, GSMEM>>>(xh_ptr, wkh_ptr, b_kqv, kqvh_ptr, C3, 1);
    }
    // 2) flash attention (fp16 MMA, fp16 softmax) -> y fp16  [8192, 1024]
    {
        dim3 grid(TT / AQ, HH, BB);
        attn_kernel<<<grid, 256, ASMEM>>>(kqvh_ptr, pad, yh_ptr);
    }
    // 3) out = y @ W_proj + b_proj  [8192, 1024], fp32 output
    {
        dim3 grid(CC / 256, M / 128);
        gemm_f16_bias<<<grid, 256, GSMEM>>>(yh_ptr, wph_ptr, b_proj, out, CC, 0);
    }
}